// round 9
// baseline (speedup 1.0000x reference)
#include <cuda_runtime.h>
#include <cuda_bf16.h>
#include <stdint.h>

// Problem constants
#define BATCH 1024
#define NA    10
#define NE    11
#define AF    32
#define EF    28
#define HYP   64
#define OUTD  256

// Concatenated-K layout:
//   [0,2048) M_ally  [2048,2080) xsum_ally  [2080,3872) M_enemy
//   [3872,3900) xsum_enemy  [3900,3904) pad
#define KA      (HYP*AF)
#define OFF_FA  KA
#define OFF_ME  (KA+AF)
#define KE      (HYP*EF)
#define OFF_FE  (OFF_ME+KE)
#define KTOT    (OFF_FE+EF)
#define KP      3904
#define SPLIT   12
#define NST     (KP/32)        // 122 BK=32 stages
#define NPACK   ((KP/64)*4)    // 244 pack tiles
#define EPB     4              // batch elements per prep block
#define NBUILD  (BATCH/EPB)    // 256

// Split-precision operands (hi + lo bf16 ~= fp32 to ~2^-17)
__device__ __align__(16) __nv_bfloat16 g_Ua_hi[BATCH * KP];   // A  [m][k]
__device__ __align__(16) __nv_bfloat16 g_Ua_lo[BATCH * KP];
__device__ __align__(16) __nv_bfloat16 g_Wt_hi[OUTD * KP];    // B^T [n][k]
__device__ __align__(16) __nv_bfloat16 g_Wt_lo[OUTD * KP];
__device__ float g_P[SPLIT * BATCH * OUTD];                   // split-K partials
__device__ int   g_cnt[32];                                   // per-tile counters (zero-init)

// ---------------------------------------------------------------------------
// helpers
// ---------------------------------------------------------------------------
__device__ __forceinline__ uint32_t smem_u32(const void* p) {
    uint32_t a;
    asm("{ .reg .u64 t; cvta.to.shared.u64 t, %1; cvt.u32.u64 %0, t; }" : "=r"(a) : "l"(p));
    return a;
}
__device__ __forceinline__ void cp16(uint32_t dst, const void* src) {
    asm volatile("cp.async.cg.shared.global [%0], [%1], 16;" :: "r"(dst), "l"(src));
}
#define CP_COMMIT() asm volatile("cp.async.commit_group;" ::: "memory")
#define CP_WAIT(N)  asm volatile("cp.async.wait_group %0;" :: "n"(N) : "memory")

__device__ __forceinline__ void ldsm4(uint32_t& r0, uint32_t& r1, uint32_t& r2,
                                      uint32_t& r3, uint32_t addr) {
    asm volatile("ldmatrix.sync.aligned.m8n8.x4.shared.b16 {%0,%1,%2,%3}, [%4];"
                 : "=r"(r0), "=r"(r1), "=r"(r2), "=r"(r3) : "r"(addr));
}
__device__ __forceinline__ void mma_bf16(float* c, const uint32_t* a, const uint32_t* b) {
    asm volatile(
        "mma.sync.aligned.m16n8k16.row.col.f32.bf16.bf16.f32 "
        "{%0,%1,%2,%3},{%4,%5,%6,%7},{%8,%9},{%0,%1,%2,%3};"
        : "+f"(c[0]), "+f"(c[1]), "+f"(c[2]), "+f"(c[3])
        : "r"(a[0]), "r"(a[1]), "r"(a[2]), "r"(a[3]), "r"(b[0]), "r"(b[1]));
}

// vectorized hi/lo emitters
__device__ __forceinline__ void emit8(__nv_bfloat16* ha, __nv_bfloat16* la,
                                      size_t idx, const float* v) {
    __align__(16) __nv_bfloat16 hv[8], lv[8];
    #pragma unroll
    for (int j = 0; j < 8; j++) {
        __nv_bfloat16 h = __float2bfloat16(v[j]);
        hv[j] = h;
        lv[j] = __float2bfloat16(v[j] - __bfloat162float(h));
    }
    *(uint4*)(ha + idx) = *(const uint4*)hv;
    *(uint4*)(la + idx) = *(const uint4*)lv;
}
__device__ __forceinline__ void emit4(__nv_bfloat16* ha, __nv_bfloat16* la,
                                      size_t idx, const float* v) {
    __align__(8) __nv_bfloat16 hv[4], lv[4];
    #pragma unroll
    for (int j = 0; j < 4; j++) {
        __nv_bfloat16 h = __float2bfloat16(v[j]);
        hv[j] = h;
        lv[j] = __float2bfloat16(v[j] - __bfloat162float(h));
    }
    *(uint2*)(ha + idx) = *(const uint2*)hv;
    *(uint2*)(la + idx) = *(const uint2*)lv;
}

// ---------------------------------------------------------------------------
// Kernel 1 "prep": blocks [0,NPACK) pack Wt hi/lo;
// blocks [NPACK, NPACK+NBUILD) build U for EPB batch elements each.
// ---------------------------------------------------------------------------
struct PrepSmem {
    union {
        float pack_s[64][65];                 // 16.6 KB
        struct {                              // 46.9 KB
            float wa1[AF * HYP];
            float we1[EF * HYP];
            float fa[EPB][NA][AF];
            float fe[EPB][NE][EF];
            float ha[EPB][NA][HYP];
            float he[EPB][NE][HYP];
        } b;
    };
};

__global__ __launch_bounds__(256) void prep(
    const float* __restrict__ fa, const float* __restrict__ fe,
    const float* __restrict__ wa1, const float* __restrict__ ba1,
    const float* __restrict__ wa2, const float* __restrict__ ba2,
    const float* __restrict__ we1, const float* __restrict__ be1,
    const float* __restrict__ we2, const float* __restrict__ be2) {

    __shared__ PrepSmem sm;
    const int t = threadIdx.x;

    if (blockIdx.x < NPACK) {
        // ---- pack: transpose + convert combined weight into Wt[n][k] ----
        const int k0 = (blockIdx.x >> 2) * 64;
        const int n0 = (blockIdx.x & 3) * 64;

        for (int i = t; i < 64 * 64; i += 256) {
            int kl = i >> 6, nl = i & 63;
            int r = k0 + kl, n = n0 + nl;
            float v;
            if (r < KA)            v = wa2[(size_t)r * OUTD + n];
            else if (r < OFF_ME)   v = ba2[(size_t)(r - KA) * OUTD + n];
            else if (r < OFF_FE)   v = we2[(size_t)(r - OFF_ME) * OUTD + n];
            else if (r < KTOT)     v = be2[(size_t)(r - OFF_FE) * OUTD + n];
            else                   v = 0.0f;
            sm.pack_s[kl][nl] = v;
        }
        __syncthreads();
        for (int i = t; i < 512; i += 256) {
            int nl = i >> 3, kl8 = (i & 7) * 8;
            float v[8];
            #pragma unroll
            for (int j = 0; j < 8; j++) v[j] = sm.pack_s[kl8 + j][nl];
            emit8(g_Wt_hi, g_Wt_lo, (size_t)(n0 + nl) * KP + k0 + kl8, v);
        }
        return;
    }

    // ---- build U for batch elements [b0, b0+EPB) ----
    const int b0 = (blockIdx.x - NPACK) * EPB;

    for (int i = t; i < AF * HYP; i += 256) sm.b.wa1[i] = wa1[i];
    for (int i = t; i < EF * HYP; i += 256) sm.b.we1[i] = we1[i];
    for (int i = t; i < EPB * NA * AF; i += 256)
        (&sm.b.fa[0][0][0])[i] = fa[(size_t)b0 * NA * AF + i];
    for (int i = t; i < EPB * NE * EF; i += 256)
        (&sm.b.fe[0][0][0])[i] = fe[(size_t)b0 * NE * EF + i];
    __syncthreads();

    // hidden layers
    for (int i = t; i < EPB * NA * HYP; i += 256) {
        int e = i / (NA * HYP), j = i % (NA * HYP);
        int n = j / HYP, k = j % HYP;
        float s = ba1[k];
        #pragma unroll
        for (int f = 0; f < AF; f++) s += sm.b.fa[e][n][f] * sm.b.wa1[f * HYP + k];
        sm.b.ha[e][n][k] = fmaxf(s, 0.0f);
    }
    for (int i = t; i < EPB * NE * HYP; i += 256) {
        int e = i / (NE * HYP), j = i % (NE * HYP);
        int n = j / HYP, k = j % HYP;
        float s = be1[k];
        #pragma unroll
        for (int f = 0; f < EF; f++) s += sm.b.fe[e][n][f] * sm.b.we1[f * HYP + k];
        sm.b.he[e][n][k] = fmaxf(s, 0.0f);
    }
    __syncthreads();

    // ally outer products: EPB*256 items, 8-wide
    for (int i = t; i < EPB * 256; i += 256) {
        int e = i >> 8, j = i & 255;
        int k = j >> 2, f8 = (j & 3) * 8;
        float s[8] = {};
        #pragma unroll
        for (int n = 0; n < NA; n++) {
            float h = sm.b.ha[e][n][k];
            #pragma unroll
            for (int q = 0; q < 8; q++) s[q] += h * sm.b.fa[e][n][f8 + q];
        }
        emit8(g_Ua_hi, g_Ua_lo, (size_t)(b0 + e) * KP + k * AF + f8, s);
    }
    // enemy outer products: EPB*448 items, 4-wide
    for (int i = t; i < EPB * 448; i += 256) {
        int e = i / 448, j = i % 448;
        int k = j / 7, f4 = (j % 7) * 4;
        float s[4] = {};
        #pragma unroll
        for (int n = 0; n < NE; n++) {
            float h = sm.b.he[e][n][k];
            #pragma unroll
            for (int q = 0; q < 4; q++) s[q] += h * sm.b.fe[e][n][f4 + q];
        }
        emit4(g_Ua_hi, g_Ua_lo, (size_t)(b0 + e) * KP + OFF_ME + k * EF + f4, s);
    }
    // xsum_ally: EPB*4 items (t in [0,16))
    if (t < EPB * 4) {
        int e = t >> 2, f8 = (t & 3) * 8;
        float s[8] = {};
        #pragma unroll
        for (int n = 0; n < NA; n++)
            #pragma unroll
            for (int q = 0; q < 8; q++) s[q] += sm.b.fa[e][n][f8 + q];
        emit8(g_Ua_hi, g_Ua_lo, (size_t)(b0 + e) * KP + OFF_FA + f8, s);
    } else if (t >= 32 && t < 32 + EPB * 7) {
        // xsum_enemy: EPB*7 items
        int i = t - 32;
        int e = i / 7, f4 = (i % 7) * 4;
        float s[4] = {};
        #pragma unroll
        for (int n = 0; n < NE; n++)
            #pragma unroll
            for (int q = 0; q < 4; q++) s[q] += sm.b.fe[e][n][f4 + q];
        emit4(g_Ua_hi, g_Ua_lo, (size_t)(b0 + e) * KP + OFF_FE + f4, s);
    } else if (t >= 64 && t < 64 + EPB) {
        // pad [3900,3904)
        float s[4] = {};
        emit4(g_Ua_hi, g_Ua_lo, (size_t)(b0 + t - 64) * KP + KTOT, s);
    }
}

// ---------------------------------------------------------------------------
// Kernel 2: split-precision bf16 HMMA GEMM, 2-stage cp.async, fused last-CTA
// split-K reduce. BM=128, BN=64, BK=32, 256 threads / 8 warps, warp 32x32.
// grid (8, 4, SPLIT=12) = 384 CTAs -> single wave at 3 CTAs/SM.
// ---------------------------------------------------------------------------
#define ASTRIDE 40                       // bf16 elems per row (80 B)
#define ASZ1    (128 * ASTRIDE * 2)      // 10240 B per A stage per array
#define BSZ1    (64 * ASTRIDE * 2)       // 5120 B per B stage per array
#define OFF_AH  0
#define OFF_AL  (2 * ASZ1)
#define OFF_BH  (4 * ASZ1)
#define OFF_BL  (4 * ASZ1 + 2 * BSZ1)
#define SMEM_DYN (4 * ASZ1 + 4 * BSZ1)   // 61440

__global__ void __launch_bounds__(256, 3) gemm_mma(float* __restrict__ out) {
    extern __shared__ char dsm[];
    __shared__ int s_old;
    const uint32_t sb = smem_u32(dsm);

    const int t    = threadIdx.x;
    const int lane = t & 31;
    const int wid  = t >> 5;
    const int wm   = (wid & 3) * 32;
    const int wn   = (wid >> 2) * 32;
    const int m0   = blockIdx.x * 128;
    const int n0   = blockIdx.y * 64;
    const int z    = blockIdx.z;
    const int s0   = (NST * z) / SPLIT;
    const int s1   = (NST * (z + 1)) / SPLIT;

    const int a_row = lane & 15;
    const int a_k8  = ((lane >> 4) & 1) * 8;
    const int b_row = (lane & 7) + ((lane >> 4) & 1) * 8;
    const int b_k8  = (lane & 8);

    float acc[2][4][4];
    #pragma unroll
    for (int i = 0; i < 2; i++)
        #pragma unroll
        for (int j = 0; j < 4; j++)
            #pragma unroll
            for (int q = 0; q < 4; q++) acc[i][j][q] = 0.0f;

    auto issue = [&](int s, int buf) {
        const int k0 = s * 32;
        #pragma unroll
        for (int q = 0; q < 2; q++) {
            int idx = t + q * 256;
            int m = idx >> 2, kc = idx & 3;
            uint32_t doff = (uint32_t)(m * ASTRIDE + kc * 8) * 2;
            const __nv_bfloat16* gh = g_Ua_hi + (size_t)(m0 + m) * KP + k0 + kc * 8;
            const __nv_bfloat16* gl = g_Ua_lo + (size_t)(m0 + m) * KP + k0 + kc * 8;
            cp16(sb + OFF_AH + buf * ASZ1 + doff, gh);
            cp16(sb + OFF_AL + buf * ASZ1 + doff, gl);
        }
        {
            int n = t >> 2, kc = t & 3;
            uint32_t doff = (uint32_t)(n * ASTRIDE + kc * 8) * 2;
            const __nv_bfloat16* gh = g_Wt_hi + (size_t)(n0 + n) * KP + k0 + kc * 8;
            const __nv_bfloat16* gl = g_Wt_lo + (size_t)(n0 + n) * KP + k0 + kc * 8;
            cp16(sb + OFF_BH + buf * BSZ1 + doff, gh);
            cp16(sb + OFF_BL + buf * BSZ1 + doff, gl);
        }
    };

    issue(s0, 0);
    CP_COMMIT();
    if (s0 + 1 < s1) issue(s0 + 1, 1);
    CP_COMMIT();

    int buf = 0;
    for (int s = s0; s < s1; s++) {
        CP_WAIT(1);            // stage s landed
        __syncthreads();

        const uint32_t baseAh = sb + OFF_AH + buf * ASZ1;
        const uint32_t baseAl = sb + OFF_AL + buf * ASZ1;
        const uint32_t baseBh = sb + OFF_BH + buf * BSZ1;
        const uint32_t baseBl = sb + OFF_BL + buf * BSZ1;

        #pragma unroll
        for (int kk = 0; kk < 2; kk++) {
            const int kcol = kk * 16;
            uint32_t A[2][4], Bh[4][2], Bl[4][2];
            #pragma unroll
            for (int p = 0; p < 2; p++) {
                uint32_t off = (uint32_t)((wn + p * 16 + b_row) * ASTRIDE + kcol + b_k8) * 2;
                ldsm4(Bh[2 * p][0], Bh[2 * p][1], Bh[2 * p + 1][0], Bh[2 * p + 1][1], baseBh + off);
                ldsm4(Bl[2 * p][0], Bl[2 * p][1], Bl[2 * p + 1][0], Bl[2 * p + 1][1], baseBl + off);
            }
            // Ah pass: AhBh + AhBl
            #pragma unroll
            for (int mt = 0; mt < 2; mt++) {
                uint32_t off = (uint32_t)((wm + mt * 16 + a_row) * ASTRIDE + kcol + a_k8) * 2;
                ldsm4(A[mt][0], A[mt][1], A[mt][2], A[mt][3], baseAh + off);
            }
            #pragma unroll
            for (int mt = 0; mt < 2; mt++)
                #pragma unroll
                for (int nt = 0; nt < 4; nt++) {
                    mma_bf16(acc[mt][nt], A[mt], Bh[nt]);
                    mma_bf16(acc[mt][nt], A[mt], Bl[nt]);
                }
            // Al pass (reuse A regs): AlBh
            #pragma unroll
            for (int mt = 0; mt < 2; mt++) {
                uint32_t off = (uint32_t)((wm + mt * 16 + a_row) * ASTRIDE + kcol + a_k8) * 2;
                ldsm4(A[mt][0], A[mt][1], A[mt][2], A[mt][3], baseAl + off);
            }
            #pragma unroll
            for (int mt = 0; mt < 2; mt++)
                #pragma unroll
                for (int nt = 0; nt < 4; nt++)
                    mma_bf16(acc[mt][nt], A[mt], Bh[nt]);
        }
        __syncthreads();       // compute(s) done: buf reusable

        if (s + 2 < s1) issue(s + 2, buf);
        CP_COMMIT();           // unconditional: uniform group counting
        buf ^= 1;
    }

    // write this CTA's split-K partial
    float* P = g_P + (size_t)z * (BATCH * OUTD);
    const int gr  = lane >> 2;
    const int tc2 = (lane & 3) * 2;
    #pragma unroll
    for (int mt = 0; mt < 2; mt++) {
        #pragma unroll
        for (int nt = 0; nt < 4; nt++) {
            int row = m0 + wm + mt * 16 + gr;
            int col = n0 + wn + nt * 8 + tc2;
            *(float2*)(P + (size_t)row * OUTD + col) =
                make_float2(acc[mt][nt][0], acc[mt][nt][1]);
            *(float2*)(P + (size_t)(row + 8) * OUTD + col) =
                make_float2(acc[mt][nt][2], acc[mt][nt][3]);
        }
    }

    // ---- fused split-K reduction: last CTA per (m,n) tile sums partials ----
    __threadfence();
    __syncthreads();
    const int tile = blockIdx.x * 4 + blockIdx.y;
    if (t == 0) s_old = atomicAdd(&g_cnt[tile], 1);
    __syncthreads();
    if (s_old == SPLIT - 1) {
        __threadfence();   // acquire: see peers' partials
        for (int i = t; i < 128 * 64 / 4; i += 256) {
            int r = i >> 4;
            int c = (i & 15) * 4;
            size_t off = (size_t)(m0 + r) * OUTD + n0 + c;
            float4 s = *(const float4*)(g_P + off);
            #pragma unroll
            for (int zz = 1; zz < SPLIT; zz++) {
                const float4 v = *(const float4*)(g_P + (size_t)zz * (BATCH * OUTD) + off);
                s.x += v.x; s.y += v.y; s.z += v.z; s.w += v.w;
            }
            *(float4*)(out + off) = s;
        }
        __syncthreads();
        if (t == 0) g_cnt[tile] = 0;   // reset for next graph replay
    }
}

// ---------------------------------------------------------------------------
// Inputs: 0 ally 1 enemy 2 wa1 3 ba1 4 wa2 5 ba2 6 we1 7 be1 8 we2 9 be2
// ---------------------------------------------------------------------------
extern "C" void kernel_launch(void* const* d_in, const int* in_sizes, int n_in,
                              void* d_out, int out_size) {
    const float* fa  = (const float*)d_in[0];
    const float* fe  = (const float*)d_in[1];
    const float* wa1 = (const float*)d_in[2];
    const float* ba1 = (const float*)d_in[3];
    const float* wa2 = (const float*)d_in[4];
    const float* ba2 = (const float*)d_in[5];
    const float* we1 = (const float*)d_in[6];
    const float* be1 = (const float*)d_in[7];
    const float* we2 = (const float*)d_in[8];
    const float* be2 = (const float*)d_in[9];
    float* out = (float*)d_out;

    cudaFuncSetAttribute(gemm_mma, cudaFuncAttributeMaxDynamicSharedMemorySize, SMEM_DYN);

    prep<<<NPACK + NBUILD, 256>>>(fa, fe, wa1, ba1, wa2, ba2, we1, be1, we2, be2);
    gemm_mma<<<dim3(BATCH / 128, OUTD / 64, SPLIT), 256, SMEM_DYN>>>(out);
}

// round 10
// speedup vs baseline: 1.0570x; 1.0570x over previous
#include <cuda_runtime.h>
#include <cuda_bf16.h>
#include <stdint.h>

// Problem constants
#define BATCH 1024
#define NA    10
#define NE    11
#define AF    32
#define EF    28
#define HYP   64
#define OUTD  256

// Concatenated-K layout:
//   [0,2048) M_ally  [2048,2080) xsum_ally  [2080,3872) M_enemy
//   [3872,3900) xsum_enemy  [3900,3904) pad
#define KA      (HYP*AF)
#define OFF_FA  KA
#define OFF_ME  (KA+AF)
#define KE      (HYP*EF)
#define OFF_FE  (OFF_ME+KE)
#define KTOT    (OFF_FE+EF)
#define KP      3904
#define SPLIT   16
#define NST     (KP/32)        // 122 BK=32 stages
#define NPACK   ((KP/64)*4)    // 244 pack tiles

// Split-precision operands (hi + lo bf16 ~= fp32 to ~2^-17)
__device__ __align__(16) __nv_bfloat16 g_Ua_hi[BATCH * KP];   // A  [m][k]
__device__ __align__(16) __nv_bfloat16 g_Ua_lo[BATCH * KP];
__device__ __align__(16) __nv_bfloat16 g_Wt_hi[OUTD * KP];    // B^T [n][k]
__device__ __align__(16) __nv_bfloat16 g_Wt_lo[OUTD * KP];
__device__ float g_P[SPLIT * BATCH * OUTD];                   // split-K partials
__device__ int   g_cnt[16];                                   // per-tile counters (zero-init)

// ---------------------------------------------------------------------------
// helpers
// ---------------------------------------------------------------------------
__device__ __forceinline__ uint32_t smem_u32(const void* p) {
    uint32_t a;
    asm("{ .reg .u64 t; cvta.to.shared.u64 t, %1; cvt.u32.u64 %0, t; }" : "=r"(a) : "l"(p));
    return a;
}
__device__ __forceinline__ void cp16(uint32_t dst, const void* src) {
    asm volatile("cp.async.cg.shared.global [%0], [%1], 16;" :: "r"(dst), "l"(src));
}
#define CP_COMMIT() asm volatile("cp.async.commit_group;" ::: "memory")
#define CP_WAIT(N)  asm volatile("cp.async.wait_group %0;" :: "n"(N) : "memory")

__device__ __forceinline__ void ldsm4(uint32_t& r0, uint32_t& r1, uint32_t& r2,
                                      uint32_t& r3, uint32_t addr) {
    asm volatile("ldmatrix.sync.aligned.m8n8.x4.shared.b16 {%0,%1,%2,%3}, [%4];"
                 : "=r"(r0), "=r"(r1), "=r"(r2), "=r"(r3) : "r"(addr));
}
__device__ __forceinline__ void mma_bf16(float* c, const uint32_t* a, const uint32_t* b) {
    asm volatile(
        "mma.sync.aligned.m16n8k16.row.col.f32.bf16.bf16.f32 "
        "{%0,%1,%2,%3},{%4,%5,%6,%7},{%8,%9},{%0,%1,%2,%3};"
        : "+f"(c[0]), "+f"(c[1]), "+f"(c[2]), "+f"(c[3])
        : "r"(a[0]), "r"(a[1]), "r"(a[2]), "r"(a[3]), "r"(b[0]), "r"(b[1]));
}

// vectorized hi/lo emitters
__device__ __forceinline__ void emit8(__nv_bfloat16* ha, __nv_bfloat16* la,
                                      size_t idx, const float* v) {
    __align__(16) __nv_bfloat16 hv[8], lv[8];
    #pragma unroll
    for (int j = 0; j < 8; j++) {
        __nv_bfloat16 h = __float2bfloat16(v[j]);
        hv[j] = h;
        lv[j] = __float2bfloat16(v[j] - __bfloat162float(h));
    }
    *(uint4*)(ha + idx) = *(const uint4*)hv;
    *(uint4*)(la + idx) = *(const uint4*)lv;
}
__device__ __forceinline__ void emit4(__nv_bfloat16* ha, __nv_bfloat16* la,
                                      size_t idx, const float* v) {
    __align__(8) __nv_bfloat16 hv[4], lv[4];
    #pragma unroll
    for (int j = 0; j < 4; j++) {
        __nv_bfloat16 h = __float2bfloat16(v[j]);
        hv[j] = h;
        lv[j] = __float2bfloat16(v[j] - __bfloat162float(h));
    }
    *(uint2*)(ha + idx) = *(const uint2*)hv;
    *(uint2*)(la + idx) = *(const uint2*)lv;
}

// ---------------------------------------------------------------------------
// Kernel 1 "prep" (R7 version): blocks [0,NPACK) pack Wt; [NPACK,+BATCH) build U.
// ---------------------------------------------------------------------------
struct PrepSmem {
    union {
        float pack_s[64][65];
        struct {
            float wa1[AF * HYP];
            float we1[EF * HYP];
            float fa[NA][AF];
            float fe[NE][EF];
            float ha[NA][HYP];
            float he[NE][HYP];
        } b;
    };
};

__global__ __launch_bounds__(256) void prep(
    const float* __restrict__ fa, const float* __restrict__ fe,
    const float* __restrict__ wa1, const float* __restrict__ ba1,
    const float* __restrict__ wa2, const float* __restrict__ ba2,
    const float* __restrict__ we1, const float* __restrict__ be1,
    const float* __restrict__ we2, const float* __restrict__ be2) {

    __shared__ PrepSmem sm;
    const int t = threadIdx.x;

    if (blockIdx.x < NPACK) {
        const int k0 = (blockIdx.x >> 2) * 64;
        const int n0 = (blockIdx.x & 3) * 64;

        for (int i = t; i < 64 * 64; i += 256) {
            int kl = i >> 6, nl = i & 63;
            int r = k0 + kl, n = n0 + nl;
            float v;
            if (r < KA)            v = wa2[(size_t)r * OUTD + n];
            else if (r < OFF_ME)   v = ba2[(size_t)(r - KA) * OUTD + n];
            else if (r < OFF_FE)   v = we2[(size_t)(r - OFF_ME) * OUTD + n];
            else if (r < KTOT)     v = be2[(size_t)(r - OFF_FE) * OUTD + n];
            else                   v = 0.0f;
            sm.pack_s[kl][nl] = v;
        }
        __syncthreads();
        for (int i = t; i < 512; i += 256) {
            int nl = i >> 3, kl8 = (i & 7) * 8;
            float v[8];
            #pragma unroll
            for (int j = 0; j < 8; j++) v[j] = sm.pack_s[kl8 + j][nl];
            emit8(g_Wt_hi, g_Wt_lo, (size_t)(n0 + nl) * KP + k0 + kl8, v);
        }
        return;
    }

    // ---- build U for batch element b ----
    const int b = blockIdx.x - NPACK;
    const size_t rb = (size_t)b * KP;

    for (int i = t; i < AF * HYP; i += 256) sm.b.wa1[i] = wa1[i];
    for (int i = t; i < EF * HYP; i += 256) sm.b.we1[i] = we1[i];
    for (int i = t; i < NA * AF; i += 256) sm.b.fa[i / AF][i % AF] = fa[b * NA * AF + i];
    for (int i = t; i < NE * EF; i += 256) sm.b.fe[i / EF][i % EF] = fe[b * NE * EF + i];
    __syncthreads();

    for (int i = t; i < NA * HYP; i += 256) {
        int n = i / HYP, k = i % HYP;
        float s = ba1[k];
        #pragma unroll
        for (int f = 0; f < AF; f++) s += sm.b.fa[n][f] * sm.b.wa1[f * HYP + k];
        sm.b.ha[n][k] = fmaxf(s, 0.0f);
    }
    for (int i = t; i < NE * HYP; i += 256) {
        int n = i / HYP, k = i % HYP;
        float s = be1[k];
        #pragma unroll
        for (int f = 0; f < EF; f++) s += sm.b.fe[n][f] * sm.b.we1[f * HYP + k];
        sm.b.he[n][k] = fmaxf(s, 0.0f);
    }
    __syncthreads();

    // ally outer products: 256 items = k(64) x f8(4), 8-wide
    {
        int k = t >> 2, f8 = (t & 3) * 8;
        float s[8] = {};
        #pragma unroll
        for (int n = 0; n < NA; n++) {
            float h = sm.b.ha[n][k];
            #pragma unroll
            for (int j = 0; j < 8; j++) s[j] += h * sm.b.fa[n][f8 + j];
        }
        emit8(g_Ua_hi, g_Ua_lo, rb + k * AF + f8, s);
    }
    // enemy outer products: 448 items = k(64) x f4(7), 4-wide
    for (int it = t; it < 448; it += 256) {
        int k = it / 7, f4 = (it - k * 7) * 4;
        float s[4] = {};
        #pragma unroll
        for (int n = 0; n < NE; n++) {
            float h = sm.b.he[n][k];
            #pragma unroll
            for (int j = 0; j < 4; j++) s[j] += h * sm.b.fe[n][f4 + j];
        }
        emit4(g_Ua_hi, g_Ua_lo, rb + OFF_ME + k * EF + f4, s);
    }
    if (t < 4) {
        int f8 = t * 8;
        float s[8] = {};
        #pragma unroll
        for (int n = 0; n < NA; n++)
            #pragma unroll
            for (int j = 0; j < 8; j++) s[j] += sm.b.fa[n][f8 + j];
        emit8(g_Ua_hi, g_Ua_lo, rb + OFF_FA + f8, s);
    } else if (t >= 8 && t < 15) {
        int f4 = (t - 8) * 4;
        float s[4] = {};
        #pragma unroll
        for (int n = 0; n < NE; n++)
            #pragma unroll
            for (int j = 0; j < 4; j++) s[j] += sm.b.fe[n][f4 + j];
        emit4(g_Ua_hi, g_Ua_lo, rb + OFF_FE + f4, s);
    } else if (t == 16) {
        float s[4] = {};
        emit4(g_Ua_hi, g_Ua_lo, rb + KTOT, s);
    }
}

// ---------------------------------------------------------------------------
// Kernel 2: split-precision bf16 HMMA GEMM. BM=128, BN=128, BK=32, 2-stage
// cp.async, 256 threads / 8 warps, warp tile 32x64 (2 mt x 8 nt).
// grid (8, 2, SPLIT=16) = 256 CTAs. Fused last-CTA split-K reduce.
// ---------------------------------------------------------------------------
#define ASTRIDE 40                       // bf16 elems per 32-k row (80 B)
#define TSZ1    (128 * ASTRIDE * 2)      // 10240 B per tile per stage (A or B)
#define OFF_AH  0
#define OFF_AL  (2 * TSZ1)
#define OFF_BH  (4 * TSZ1)
#define OFF_BL  (6 * TSZ1)
#define SMEM_DYN (8 * TSZ1)              // 81920

__global__ void __launch_bounds__(256, 2) gemm_mma(float* __restrict__ out) {
    extern __shared__ char dsm[];
    __shared__ int s_old;
    const uint32_t sb = smem_u32(dsm);

    const int t    = threadIdx.x;
    const int lane = t & 31;
    const int wid  = t >> 5;
    const int wm   = (wid & 3) * 32;       // 4 m-warps
    const int wn   = (wid >> 2) * 64;      // 2 n-warps
    const int m0   = blockIdx.x * 128;
    const int n0   = blockIdx.y * 128;
    const int z    = blockIdx.z;
    const int s0   = (NST * z) / SPLIT;
    const int s1   = (NST * (z + 1)) / SPLIT;

    const int a_row = lane & 15;
    const int a_k8  = ((lane >> 4) & 1) * 8;
    const int b_row = (lane & 7) + ((lane >> 4) & 1) * 8;
    const int b_k8  = (lane & 8);

    float acc[2][8][4];
    #pragma unroll
    for (int i = 0; i < 2; i++)
        #pragma unroll
        for (int j = 0; j < 8; j++)
            #pragma unroll
            for (int q = 0; q < 4; q++) acc[i][j][q] = 0.0f;

    // stage loader: A and B tiles are both 128 rows x 32 k
    auto issue = [&](int s, int buf) {
        const int k0 = s * 32;
        #pragma unroll
        for (int q = 0; q < 2; q++) {
            int idx = t + q * 256;               // [0,512)
            int r = idx >> 2, kc = idx & 3;
            uint32_t doff = (uint32_t)(r * ASTRIDE + kc * 8) * 2;
            size_t goff = (size_t)kc * 8 + k0;
            cp16(sb + OFF_AH + buf * TSZ1 + doff, g_Ua_hi + (size_t)(m0 + r) * KP + goff);
            cp16(sb + OFF_AL + buf * TSZ1 + doff, g_Ua_lo + (size_t)(m0 + r) * KP + goff);
            cp16(sb + OFF_BH + buf * TSZ1 + doff, g_Wt_hi + (size_t)(n0 + r) * KP + goff);
            cp16(sb + OFF_BL + buf * TSZ1 + doff, g_Wt_lo + (size_t)(n0 + r) * KP + goff);
        }
    };

    issue(s0, 0);
    CP_COMMIT();
    if (s0 + 1 < s1) issue(s0 + 1, 1);
    CP_COMMIT();

    int buf = 0;
    for (int s = s0; s < s1; s++) {
        CP_WAIT(1);            // stage s landed
        __syncthreads();

        const uint32_t baseAh = sb + OFF_AH + buf * TSZ1;
        const uint32_t baseAl = sb + OFF_AL + buf * TSZ1;
        const uint32_t baseBh = sb + OFF_BH + buf * TSZ1;
        const uint32_t baseBl = sb + OFF_BL + buf * TSZ1;

        #pragma unroll
        for (int kk = 0; kk < 2; kk++) {
            const int kcol = kk * 16;
            uint32_t A[2][4], Bh[8][2], Bl[8][2];
            #pragma unroll
            for (int p = 0; p < 4; p++) {
                uint32_t off = (uint32_t)((wn + p * 16 + b_row) * ASTRIDE + kcol + b_k8) * 2;
                ldsm4(Bh[2 * p][0], Bh[2 * p][1], Bh[2 * p + 1][0], Bh[2 * p + 1][1], baseBh + off);
                ldsm4(Bl[2 * p][0], Bl[2 * p][1], Bl[2 * p + 1][0], Bl[2 * p + 1][1], baseBl + off);
            }
            // Ah pass: AhBh + AhBl
            #pragma unroll
            for (int mt = 0; mt < 2; mt++) {
                uint32_t off = (uint32_t)((wm + mt * 16 + a_row) * ASTRIDE + kcol + a_k8) * 2;
                ldsm4(A[mt][0], A[mt][1], A[mt][2], A[mt][3], baseAh + off);
            }
            #pragma unroll
            for (int mt = 0; mt < 2; mt++)
                #pragma unroll
                for (int nt = 0; nt < 8; nt++) {
                    mma_bf16(acc[mt][nt], A[mt], Bh[nt]);
                    mma_bf16(acc[mt][nt], A[mt], Bl[nt]);
                }
            // Al pass (reuse A regs): AlBh
            #pragma unroll
            for (int mt = 0; mt < 2; mt++) {
                uint32_t off = (uint32_t)((wm + mt * 16 + a_row) * ASTRIDE + kcol + a_k8) * 2;
                ldsm4(A[mt][0], A[mt][1], A[mt][2], A[mt][3], baseAl + off);
            }
            #pragma unroll
            for (int mt = 0; mt < 2; mt++)
                #pragma unroll
                for (int nt = 0; nt < 8; nt++)
                    mma_bf16(acc[mt][nt], A[mt], Bh[nt]);
        }
        __syncthreads();       // compute(s) done: buf reusable

        if (s + 2 < s1) issue(s + 2, buf);
        CP_COMMIT();           // unconditional: uniform group counting
        buf ^= 1;
    }

    // write this CTA's split-K partial
    float* P = g_P + (size_t)z * (BATCH * OUTD);
    const int gr  = lane >> 2;
    const int tc2 = (lane & 3) * 2;
    #pragma unroll
    for (int mt = 0; mt < 2; mt++) {
        #pragma unroll
        for (int nt = 0; nt < 8; nt++) {
            int row = m0 + wm + mt * 16 + gr;
            int col = n0 + wn + nt * 8 + tc2;
            *(float2*)(P + (size_t)row * OUTD + col) =
                make_float2(acc[mt][nt][0], acc[mt][nt][1]);
            *(float2*)(P + (size_t)(row + 8) * OUTD + col) =
                make_float2(acc[mt][nt][2], acc[mt][nt][3]);
        }
    }

    // ---- fused split-K reduction: last CTA per (m,n) tile sums partials ----
    __threadfence();
    __syncthreads();
    const int tile = blockIdx.x * 2 + blockIdx.y;
    if (t == 0) s_old = atomicAdd(&g_cnt[tile], 1);
    __syncthreads();
    if (s_old == SPLIT - 1) {
        __threadfence();   // acquire: see peers' partials
        for (int i = t; i < 128 * 128 / 4; i += 256) {
            int r = i >> 5;
            int c = (i & 31) * 4;
            size_t off = (size_t)(m0 + r) * OUTD + n0 + c;
            float4 s = *(const float4*)(g_P + off);
            #pragma unroll
            for (int zz = 1; zz < SPLIT; zz++) {
                const float4 v = *(const float4*)(g_P + (size_t)zz * (BATCH * OUTD) + off);
                s.x += v.x; s.y += v.y; s.z += v.z; s.w += v.w;
            }
            *(float4*)(out + off) = s;
        }
        __syncthreads();
        if (t == 0) g_cnt[tile] = 0;   // reset for next graph replay
    }
}

// ---------------------------------------------------------------------------
// Inputs: 0 ally 1 enemy 2 wa1 3 ba1 4 wa2 5 ba2 6 we1 7 be1 8 we2 9 be2
// ---------------------------------------------------------------------------
extern "C" void kernel_launch(void* const* d_in, const int* in_sizes, int n_in,
                              void* d_out, int out_size) {
    const float* fa  = (const float*)d_in[0];
    const float* fe  = (const float*)d_in[1];
    const float* wa1 = (const float*)d_in[2];
    const float* ba1 = (const float*)d_in[3];
    const float* wa2 = (const float*)d_in[4];
    const float* ba2 = (const float*)d_in[5];
    const float* we1 = (const float*)d_in[6];
    const float* be1 = (const float*)d_in[7];
    const float* we2 = (const float*)d_in[8];
    const float* be2 = (const float*)d_in[9];
    float* out = (float*)d_out;

    cudaFuncSetAttribute(gemm_mma, cudaFuncAttributeMaxDynamicSharedMemorySize, SMEM_DYN);

    prep<<<NPACK + BATCH, 256>>>(fa, fe, wa1, ba1, wa2, ba2, we1, be1, we2, be2);
    gemm_mma<<<dim3(BATCH / 128, OUTD / 128, SPLIT), 256, SMEM_DYN>>>(out);
}

// round 12
// speedup vs baseline: 1.0883x; 1.0296x over previous
#include <cuda_runtime.h>
#include <cuda_bf16.h>
#include <stdint.h>

// Problem constants
#define BATCH 1024
#define NA    10
#define NE    11
#define AF    32
#define EF    28
#define HYP   64
#define OUTD  256

// Concatenated-K layout:
//   [0,2048) M_ally  [2048,2080) xsum_ally  [2080,3872) M_enemy
//   [3872,3900) xsum_enemy  [3900,3904) pad
#define KA      (HYP*AF)
#define OFF_FA  KA
#define OFF_ME  (KA+AF)
#define KE      (HYP*EF)
#define OFF_FE  (OFF_ME+KE)
#define KTOT    (OFF_FE+EF)
#define KP      3904
#define SPLIT   12
#define NST     (KP/32)        // 122 BK=32 stages
#define NPACK   ((KP/64)*4)    // 244 pack tiles

// Split-precision operands (hi + lo bf16 ~= fp32 to ~2^-17)
__device__ __align__(16) __nv_bfloat16 g_Ua_hi[BATCH * KP];   // A  [m][k]
__device__ __align__(16) __nv_bfloat16 g_Ua_lo[BATCH * KP];
__device__ __align__(16) __nv_bfloat16 g_Wt_hi[OUTD * KP];    // B^T [n][k]
__device__ __align__(16) __nv_bfloat16 g_Wt_lo[OUTD * KP];
__device__ float g_P[SPLIT * BATCH * OUTD];                   // split-K partials
__device__ int   g_cnt[32];                                   // per-tile counters (zero-init)

// ---------------------------------------------------------------------------
// helpers
// ---------------------------------------------------------------------------
__device__ __forceinline__ uint32_t smem_u32(const void* p) {
    uint32_t a;
    asm("{ .reg .u64 t; cvta.to.shared.u64 t, %1; cvt.u32.u64 %0, t; }" : "=r"(a) : "l"(p));
    return a;
}
__device__ __forceinline__ void cp16(uint32_t dst, const void* src) {
    asm volatile("cp.async.cg.shared.global [%0], [%1], 16;" :: "r"(dst), "l"(src));
}
#define CP_COMMIT() asm volatile("cp.async.commit_group;" ::: "memory")
#define CP_WAIT(N)  asm volatile("cp.async.wait_group %0;" :: "n"(N) : "memory")

__device__ __forceinline__ void ldsm4(uint32_t& r0, uint32_t& r1, uint32_t& r2,
                                      uint32_t& r3, uint32_t addr) {
    asm volatile("ldmatrix.sync.aligned.m8n8.x4.shared.b16 {%0,%1,%2,%3}, [%4];"
                 : "=r"(r0), "=r"(r1), "=r"(r2), "=r"(r3) : "r"(addr));
}
__device__ __forceinline__ void mma_bf16(float* c, const uint32_t* a, const uint32_t* b) {
    asm volatile(
        "mma.sync.aligned.m16n8k16.row.col.f32.bf16.bf16.f32 "
        "{%0,%1,%2,%3},{%4,%5,%6,%7},{%8,%9},{%0,%1,%2,%3};"
        : "+f"(c[0]), "+f"(c[1]), "+f"(c[2]), "+f"(c[3])
        : "r"(a[0]), "r"(a[1]), "r"(a[2]), "r"(a[3]), "r"(b[0]), "r"(b[1]));
}

// vectorized hi/lo emitters
__device__ __forceinline__ void emit8(__nv_bfloat16* ha, __nv_bfloat16* la,
                                      size_t idx, const float* v) {
    __align__(16) __nv_bfloat16 hv[8], lv[8];
    #pragma unroll
    for (int j = 0; j < 8; j++) {
        __nv_bfloat16 h = __float2bfloat16(v[j]);
        hv[j] = h;
        lv[j] = __float2bfloat16(v[j] - __bfloat162float(h));
    }
    *(uint4*)(ha + idx) = *(const uint4*)hv;
    *(uint4*)(la + idx) = *(const uint4*)lv;
}
__device__ __forceinline__ void emit4(__nv_bfloat16* ha, __nv_bfloat16* la,
                                      size_t idx, const float* v) {
    __align__(8) __nv_bfloat16 hv[4], lv[4];
    #pragma unroll
    for (int j = 0; j < 4; j++) {
        __nv_bfloat16 h = __float2bfloat16(v[j]);
        hv[j] = h;
        lv[j] = __float2bfloat16(v[j] - __bfloat162float(h));
    }
    *(uint2*)(ha + idx) = *(const uint2*)hv;
    *(uint2*)(la + idx) = *(const uint2*)lv;
}

// ---------------------------------------------------------------------------
// Kernel 1 "prep": blocks [0,BATCH) build U (long pole, scheduled first);
// blocks [BATCH, BATCH+NPACK) pack Wt.
// ---------------------------------------------------------------------------
struct PrepSmem {
    union {
        float pack_s[64][65];
        struct {
            float wa1[AF * HYP];
            float we1[EF * HYP];
            float fa[NA][AF];
            float fe[NE][EF];
            float ha[NA][HYP];
            float he[NE][HYP];
        } b;
    };
};

__global__ __launch_bounds__(256) void prep(
    const float* __restrict__ fa, const float* __restrict__ fe,
    const float* __restrict__ wa1, const float* __restrict__ ba1,
    const float* __restrict__ wa2, const float* __restrict__ ba2,
    const float* __restrict__ we1, const float* __restrict__ be1,
    const float* __restrict__ we2, const float* __restrict__ be2) {

    __shared__ PrepSmem sm;
    const int t = threadIdx.x;

    if (blockIdx.x >= BATCH) {
        // ---- pack: transpose + convert combined weight into Wt[n][k] ----
        const int pb = blockIdx.x - BATCH;
        const int k0 = (pb >> 2) * 64;
        const int n0 = (pb & 3) * 64;

        for (int i = t; i < 64 * 64; i += 256) {
            int kl = i >> 6, nl = i & 63;
            int r = k0 + kl, n = n0 + nl;
            float v;
            if (r < KA)            v = wa2[(size_t)r * OUTD + n];
            else if (r < OFF_ME)   v = ba2[(size_t)(r - KA) * OUTD + n];
            else if (r < OFF_FE)   v = we2[(size_t)(r - OFF_ME) * OUTD + n];
            else if (r < KTOT)     v = be2[(size_t)(r - OFF_FE) * OUTD + n];
            else                   v = 0.0f;
            sm.pack_s[kl][nl] = v;
        }
        __syncthreads();
        for (int i = t; i < 512; i += 256) {
            int nl = i >> 3, kl8 = (i & 7) * 8;
            float v[8];
            #pragma unroll
            for (int j = 0; j < 8; j++) v[j] = sm.pack_s[kl8 + j][nl];
            emit8(g_Wt_hi, g_Wt_lo, (size_t)(n0 + nl) * KP + k0 + kl8, v);
        }
        return;
    }

    // ---- build U for batch element b ----
    const int b = blockIdx.x;
    const size_t rb = (size_t)b * KP;

    for (int i = t; i < AF * HYP; i += 256) sm.b.wa1[i] = wa1[i];
    for (int i = t; i < EF * HYP; i += 256) sm.b.we1[i] = we1[i];
    for (int i = t; i < NA * AF; i += 256) sm.b.fa[i / AF][i % AF] = fa[b * NA * AF + i];
    for (int i = t; i < NE * EF; i += 256) sm.b.fe[i / EF][i % EF] = fe[b * NE * EF + i];
    __syncthreads();

    for (int i = t; i < NA * HYP; i += 256) {
        int n = i / HYP, k = i % HYP;
        float s = ba1[k];
        #pragma unroll
        for (int f = 0; f < AF; f++) s += sm.b.fa[n][f] * sm.b.wa1[f * HYP + k];
        sm.b.ha[n][k] = fmaxf(s, 0.0f);
    }
    for (int i = t; i < NE * HYP; i += 256) {
        int n = i / HYP, k = i % HYP;
        float s = be1[k];
        #pragma unroll
        for (int f = 0; f < EF; f++) s += sm.b.fe[n][f] * sm.b.we1[f * HYP + k];
        sm.b.he[n][k] = fmaxf(s, 0.0f);
    }
    __syncthreads();

    // ally outer products: 256 items = k(64) x f8(4), 8-wide
    {
        int k = t >> 2, f8 = (t & 3) * 8;
        float s[8] = {};
        #pragma unroll
        for (int n = 0; n < NA; n++) {
            float h = sm.b.ha[n][k];
            #pragma unroll
            for (int j = 0; j < 8; j++) s[j] += h * sm.b.fa[n][f8 + j];
        }
        emit8(g_Ua_hi, g_Ua_lo, rb + k * AF + f8, s);
    }
    // enemy outer products: 448 items = k(64) x f4(7), 4-wide
    for (int it = t; it < 448; it += 256) {
        int k = it / 7, f4 = (it - k * 7) * 4;
        float s[4] = {};
        #pragma unroll
        for (int n = 0; n < NE; n++) {
            float h = sm.b.he[n][k];
            #pragma unroll
            for (int j = 0; j < 4; j++) s[j] += h * sm.b.fe[n][f4 + j];
        }
        emit4(g_Ua_hi, g_Ua_lo, rb + OFF_ME + k * EF + f4, s);
    }
    if (t < 4) {
        int f8 = t * 8;
        float s[8] = {};
        #pragma unroll
        for (int n = 0; n < NA; n++)
            #pragma unroll
            for (int j = 0; j < 8; j++) s[j] += sm.b.fa[n][f8 + j];
        emit8(g_Ua_hi, g_Ua_lo, rb + OFF_FA + f8, s);
    } else if (t >= 8 && t < 15) {
        int f4 = (t - 8) * 4;
        float s[4] = {};
        #pragma unroll
        for (int n = 0; n < NE; n++)
            #pragma unroll
            for (int j = 0; j < 4; j++) s[j] += sm.b.fe[n][f4 + j];
        emit4(g_Ua_hi, g_Ua_lo, rb + OFF_FE + f4, s);
    } else if (t == 16) {
        float s[4] = {};
        emit4(g_Ua_hi, g_Ua_lo, rb + KTOT, s);
    }
}

// ---------------------------------------------------------------------------
// Kernel 2: split-precision bf16 HMMA GEMM. BM=128, BN=64, BK=32, 2-stage
// cp.async, 256 threads / 8 warps, warp tile 32x32 (2mt x 4nt).
// Inner loop issues mma in accumulator-sweeping passes so consecutive
// instructions never RAW the same accumulator (mma latency hiding).
// grid (8, 4, SPLIT=12) = 384 CTAs. Fused last-CTA split-K reduce.
// ---------------------------------------------------------------------------
#define ASTRIDE 40                       // bf16 elems per row (80 B)
#define ASZ1    (128 * ASTRIDE * 2)      // 10240 B per A stage per array
#define BSZ1    (64 * ASTRIDE * 2)       // 5120 B per B stage per array
#define OFF_AH  0
#define OFF_AL  (2 * ASZ1)
#define OFF_BH  (4 * ASZ1)
#define OFF_BL  (4 * ASZ1 + 2 * BSZ1)
#define SMEM_DYN (4 * ASZ1 + 4 * BSZ1)   // 61440

__global__ void __launch_bounds__(256, 3) gemm_mma(float* __restrict__ out) {
    extern __shared__ char dsm[];
    __shared__ int s_old;
    const uint32_t sb = smem_u32(dsm);

    const int t    = threadIdx.x;
    const int lane = t & 31;
    const int wid  = t >> 5;
    const int wm   = (wid & 3) * 32;
    const int wn   = (wid >> 2) * 32;
    const int m0   = blockIdx.x * 128;
    const int n0   = blockIdx.y * 64;
    const int z    = blockIdx.z;
    const int s0   = (NST * z) / SPLIT;
    const int s1   = (NST * (z + 1)) / SPLIT;

    const int a_row = lane & 15;
    const int a_k8  = ((lane >> 4) & 1) * 8;
    const int b_row = (lane & 7) + ((lane >> 4) & 1) * 8;
    const int b_k8  = (lane & 8);

    float acc[2][4][4];
    #pragma unroll
    for (int i = 0; i < 2; i++)
        #pragma unroll
        for (int j = 0; j < 4; j++)
            #pragma unroll
            for (int q = 0; q < 4; q++) acc[i][j][q] = 0.0f;

    auto issue = [&](int s, int buf) {
        const int k0 = s * 32;
        #pragma unroll
        for (int q = 0; q < 2; q++) {
            int idx = t + q * 256;
            int m = idx >> 2, kc = idx & 3;
            uint32_t doff = (uint32_t)(m * ASTRIDE + kc * 8) * 2;
            const __nv_bfloat16* gh = g_Ua_hi + (size_t)(m0 + m) * KP + k0 + kc * 8;
            const __nv_bfloat16* gl = g_Ua_lo + (size_t)(m0 + m) * KP + k0 + kc * 8;
            cp16(sb + OFF_AH + buf * ASZ1 + doff, gh);
            cp16(sb + OFF_AL + buf * ASZ1 + doff, gl);
        }
        {
            int n = t >> 2, kc = t & 3;
            uint32_t doff = (uint32_t)(n * ASTRIDE + kc * 8) * 2;
            const __nv_bfloat16* gh = g_Wt_hi + (size_t)(n0 + n) * KP + k0 + kc * 8;
            const __nv_bfloat16* gl = g_Wt_lo + (size_t)(n0 + n) * KP + k0 + kc * 8;
            cp16(sb + OFF_BH + buf * BSZ1 + doff, gh);
            cp16(sb + OFF_BL + buf * BSZ1 + doff, gl);
        }
    };

    issue(s0, 0);
    CP_COMMIT();
    if (s0 + 1 < s1) issue(s0 + 1, 1);
    CP_COMMIT();

    int buf = 0;
    for (int s = s0; s < s1; s++) {
        CP_WAIT(1);            // stage s landed
        __syncthreads();

        const uint32_t baseAh = sb + OFF_AH + buf * ASZ1;
        const uint32_t baseAl = sb + OFF_AL + buf * ASZ1;
        const uint32_t baseBh = sb + OFF_BH + buf * BSZ1;
        const uint32_t baseBl = sb + OFF_BL + buf * BSZ1;

        #pragma unroll
        for (int kk = 0; kk < 2; kk++) {
            const int kcol = kk * 16;
            uint32_t A[2][4], Bh[4][2], Bl[4][2];
            #pragma unroll
            for (int p = 0; p < 2; p++) {
                uint32_t off = (uint32_t)((wn + p * 16 + b_row) * ASTRIDE + kcol + b_k8) * 2;
                ldsm4(Bh[2 * p][0], Bh[2 * p][1], Bh[2 * p + 1][0], Bh[2 * p + 1][1], baseBh + off);
                ldsm4(Bl[2 * p][0], Bl[2 * p][1], Bl[2 * p + 1][0], Bl[2 * p + 1][1], baseBl + off);
            }
            #pragma unroll
            for (int mt = 0; mt < 2; mt++) {
                uint32_t off = (uint32_t)((wm + mt * 16 + a_row) * ASTRIDE + kcol + a_k8) * 2;
                ldsm4(A[mt][0], A[mt][1], A[mt][2], A[mt][3], baseAh + off);
            }
            // pass 1: Ah*Bh — 8 distinct accumulators back-to-back
            #pragma unroll
            for (int mt = 0; mt < 2; mt++)
                #pragma unroll
                for (int nt = 0; nt < 4; nt++)
                    mma_bf16(acc[mt][nt], A[mt], Bh[nt]);
            // pass 2: Ah*Bl — 8 instructions since last same-acc write
            #pragma unroll
            for (int mt = 0; mt < 2; mt++)
                #pragma unroll
                for (int nt = 0; nt < 4; nt++)
                    mma_bf16(acc[mt][nt], A[mt], Bl[nt]);
            // reload A regs with Al
            #pragma unroll
            for (int mt = 0; mt < 2; mt++) {
                uint32_t off = (uint32_t)((wm + mt * 16 + a_row) * ASTRIDE + kcol + a_k8) * 2;
                ldsm4(A[mt][0], A[mt][1], A[mt][2], A[mt][3], baseAl + off);
            }
            // pass 3: Al*Bh
            #pragma unroll
            for (int mt = 0; mt < 2; mt++)
                #pragma unroll
                for (int nt = 0; nt < 4; nt++)
                    mma_bf16(acc[mt][nt], A[mt], Bh[nt]);
        }
        __syncthreads();       // compute(s) done: buf reusable

        if (s + 2 < s1) issue(s + 2, buf);
        CP_COMMIT();           // unconditional: uniform group counting
        buf ^= 1;
    }

    // write this CTA's split-K partial
    float* P = g_P + (size_t)z * (BATCH * OUTD);
    const int gr  = lane >> 2;
    const int tc2 = (lane & 3) * 2;
    #pragma unroll
    for (int mt = 0; mt < 2; mt++) {
        #pragma unroll
        for (int nt = 0; nt < 4; nt++) {
            int row = m0 + wm + mt * 16 + gr;
            int col = n0 + wn + nt * 8 + tc2;
            *(float2*)(P + (size_t)row * OUTD + col) =
                make_float2(acc[mt][nt][0], acc[mt][nt][1]);
            *(float2*)(P + (size_t)(row + 8) * OUTD + col) =
                make_float2(acc[mt][nt][2], acc[mt][nt][3]);
        }
    }

    // ---- fused split-K reduction: last CTA per (m,n) tile sums partials ----
    __threadfence();
    __syncthreads();
    const int tile = blockIdx.x * 4 + blockIdx.y;
    if (t == 0) s_old = atomicAdd(&g_cnt[tile], 1);
    __syncthreads();
    if (s_old == SPLIT - 1) {
        __threadfence();   // acquire: see peers' partials
        for (int i = t; i < 128 * 64 / 4; i += 256) {
            int r = i >> 4;
            int c = (i & 15) * 4;
            size_t off = (size_t)(m0 + r) * OUTD + n0 + c;
            float4 s = *(const float4*)(g_P + off);
            #pragma unroll
            for (int zz = 1; zz < SPLIT; zz++) {
                const float4 v = *(const float4*)(g_P + (size_t)zz * (BATCH * OUTD) + off);
                s.x += v.x; s.y += v.y; s.z += v.z; s.w += v.w;
            }
            *(float4*)(out + off) = s;
        }
        __syncthreads();
        if (t == 0) g_cnt[tile] = 0;   // reset for next graph replay
    }
}

// ---------------------------------------------------------------------------
// Inputs: 0 ally 1 enemy 2 wa1 3 ba1 4 wa2 5 ba2 6 we1 7 be1 8 we2 9 be2
// ---------------------------------------------------------------------------
extern "C" void kernel_launch(void* const* d_in, const int* in_sizes, int n_in,
                              void* d_out, int out_size) {
    const float* fa  = (const float*)d_in[0];
    const float* fe  = (const float*)d_in[1];
    const float* wa1 = (const float*)d_in[2];
    const float* ba1 = (const float*)d_in[3];
    const float* wa2 = (const float*)d_in[4];
    const float* ba2 = (const float*)d_in[5];
    const float* we1 = (const float*)d_in[6];
    const float* be1 = (const float*)d_in[7];
    const float* we2 = (const float*)d_in[8];
    const float* be2 = (const float*)d_in[9];
    float* out = (float*)d_out;

    cudaFuncSetAttribute(gemm_mma, cudaFuncAttributeMaxDynamicSharedMemorySize, SMEM_DYN);

    prep<<<BATCH + NPACK, 256>>>(fa, fe, wa1, ba1, wa2, ba2, we1, be1, we2, be2);
    gemm_mma<<<dim3(BATCH / 128, OUTD / 64, SPLIT), 256, SMEM_DYN>>>(out);
}

// round 13
// speedup vs baseline: 1.2865x; 1.1821x over previous
#include <cuda_runtime.h>
#include <cuda_fp16.h>
#include <stdint.h>

// Problem constants
#define BATCH 1024
#define NA    10
#define NE    11
#define AF    32
#define EF    28
#define HYP   64
#define OUTD  256

// Concatenated-K layout:
//   [0,2048) M_ally  [2048,2080) xsum_ally  [2080,3872) M_enemy
//   [3872,3900) xsum_enemy  [3900,3904) pad
#define KA      (HYP*AF)
#define OFF_FA  KA
#define OFF_ME  (KA+AF)
#define KE      (HYP*EF)
#define OFF_FE  (OFF_ME+KE)
#define KTOT    (OFF_FE+EF)
#define KP      3904
#define SPLIT   12
#define NST     (KP/32)        // 122 BK=32 stages
#define NPACK   ((KP/64)*4)    // 244 pack tiles

// fp16 operands: A = U single (error ~A's fp16 rounding, ~5e-4 after GEMM);
// B = W split hi+lo (exact to ~2^-22).
__device__ __align__(16) __half g_Ua[BATCH * KP];     // A [m][k], single fp16
__device__ __align__(16) __half g_Wt_h[OUTD * KP];    // B^T [n][k] hi
__device__ __align__(16) __half g_Wt_l[OUTD * KP];    // B^T [n][k] lo
__device__ float g_P[SPLIT * BATCH * OUTD];           // split-K partials
__device__ int   g_cnt[32];                           // per-tile counters (zero-init)

// ---------------------------------------------------------------------------
// helpers
// ---------------------------------------------------------------------------
__device__ __forceinline__ uint32_t smem_u32(const void* p) {
    uint32_t a;
    asm("{ .reg .u64 t; cvta.to.shared.u64 t, %1; cvt.u32.u64 %0, t; }" : "=r"(a) : "l"(p));
    return a;
}
__device__ __forceinline__ void cp16(uint32_t dst, const void* src) {
    asm volatile("cp.async.cg.shared.global [%0], [%1], 16;" :: "r"(dst), "l"(src));
}
#define CP_COMMIT() asm volatile("cp.async.commit_group;" ::: "memory")
#define CP_WAIT(N)  asm volatile("cp.async.wait_group %0;" :: "n"(N) : "memory")

__device__ __forceinline__ void ldsm4(uint32_t& r0, uint32_t& r1, uint32_t& r2,
                                      uint32_t& r3, uint32_t addr) {
    asm volatile("ldmatrix.sync.aligned.m8n8.x4.shared.b16 {%0,%1,%2,%3}, [%4];"
                 : "=r"(r0), "=r"(r1), "=r"(r2), "=r"(r3) : "r"(addr));
}
__device__ __forceinline__ void mma_f16(float* c, const uint32_t* a, const uint32_t* b) {
    asm volatile(
        "mma.sync.aligned.m16n8k16.row.col.f32.f16.f16.f32 "
        "{%0,%1,%2,%3},{%4,%5,%6,%7},{%8,%9},{%0,%1,%2,%3};"
        : "+f"(c[0]), "+f"(c[1]), "+f"(c[2]), "+f"(c[3])
        : "r"(a[0]), "r"(a[1]), "r"(a[2]), "r"(a[3]), "r"(b[0]), "r"(b[1]));
}

// single-array fp16 emitters (for U)
__device__ __forceinline__ void emit8h(__half* p, size_t idx, const float* v) {
    __align__(16) __half hv[8];
    #pragma unroll
    for (int j = 0; j < 8; j++) hv[j] = __float2half_rn(v[j]);
    *(uint4*)(p + idx) = *(const uint4*)hv;
}
__device__ __forceinline__ void emit4h(__half* p, size_t idx, const float* v) {
    __align__(8) __half hv[4];
    #pragma unroll
    for (int j = 0; j < 4; j++) hv[j] = __float2half_rn(v[j]);
    *(uint2*)(p + idx) = *(const uint2*)hv;
}
// hi/lo fp16 emitter (for W)
__device__ __forceinline__ void emit8hl(__half* ph, __half* pl, size_t idx, const float* v) {
    __align__(16) __half hv[8], lv[8];
    #pragma unroll
    for (int j = 0; j < 8; j++) {
        __half h = __float2half_rn(v[j]);
        hv[j] = h;
        lv[j] = __float2half_rn(v[j] - __half2float(h));
    }
    *(uint4*)(ph + idx) = *(const uint4*)hv;
    *(uint4*)(pl + idx) = *(const uint4*)lv;
}

// ---------------------------------------------------------------------------
// Kernel 1 "prep": blocks [0,BATCH) build U; [BATCH,BATCH+NPACK) pack Wt.
// ---------------------------------------------------------------------------
struct PrepSmem {
    union {
        float pack_s[64][65];
        struct {
            float wa1[AF * HYP];
            float we1[EF * HYP];
            float fa[NA][AF];
            float fe[NE][EF];
            float ha[NA][HYP];
            float he[NE][HYP];
        } b;
    };
};

__global__ __launch_bounds__(256) void prep(
    const float* __restrict__ fa, const float* __restrict__ fe,
    const float* __restrict__ wa1, const float* __restrict__ ba1,
    const float* __restrict__ wa2, const float* __restrict__ ba2,
    const float* __restrict__ we1, const float* __restrict__ be1,
    const float* __restrict__ we2, const float* __restrict__ be2) {

    __shared__ PrepSmem sm;
    const int t = threadIdx.x;

    if (blockIdx.x >= BATCH) {
        // ---- pack: transpose + convert combined weight into Wt[n][k] hi/lo ----
        const int pb = blockIdx.x - BATCH;
        const int k0 = (pb >> 2) * 64;
        const int n0 = (pb & 3) * 64;

        for (int i = t; i < 64 * 64; i += 256) {
            int kl = i >> 6, nl = i & 63;
            int r = k0 + kl, n = n0 + nl;
            float v;
            if (r < KA)            v = wa2[(size_t)r * OUTD + n];
            else if (r < OFF_ME)   v = ba2[(size_t)(r - KA) * OUTD + n];
            else if (r < OFF_FE)   v = we2[(size_t)(r - OFF_ME) * OUTD + n];
            else if (r < KTOT)     v = be2[(size_t)(r - OFF_FE) * OUTD + n];
            else                   v = 0.0f;
            sm.pack_s[kl][nl] = v;
        }
        __syncthreads();
        for (int i = t; i < 512; i += 256) {
            int nl = i >> 3, kl8 = (i & 7) * 8;
            float v[8];
            #pragma unroll
            for (int j = 0; j < 8; j++) v[j] = sm.pack_s[kl8 + j][nl];
            emit8hl(g_Wt_h, g_Wt_l, (size_t)(n0 + nl) * KP + k0 + kl8, v);
        }
        return;
    }

    // ---- build U for batch element b ----
    const int b = blockIdx.x;
    const size_t rb = (size_t)b * KP;

    for (int i = t; i < AF * HYP; i += 256) sm.b.wa1[i] = wa1[i];
    for (int i = t; i < EF * HYP; i += 256) sm.b.we1[i] = we1[i];
    for (int i = t; i < NA * AF; i += 256) sm.b.fa[i / AF][i % AF] = fa[b * NA * AF + i];
    for (int i = t; i < NE * EF; i += 256) sm.b.fe[i / EF][i % EF] = fe[b * NE * EF + i];
    __syncthreads();

    for (int i = t; i < NA * HYP; i += 256) {
        int n = i / HYP, k = i % HYP;
        float s = ba1[k];
        #pragma unroll
        for (int f = 0; f < AF; f++) s += sm.b.fa[n][f] * sm.b.wa1[f * HYP + k];
        sm.b.ha[n][k] = fmaxf(s, 0.0f);
    }
    for (int i = t; i < NE * HYP; i += 256) {
        int n = i / HYP, k = i % HYP;
        float s = be1[k];
        #pragma unroll
        for (int f = 0; f < EF; f++) s += sm.b.fe[n][f] * sm.b.we1[f * HYP + k];
        sm.b.he[n][k] = fmaxf(s, 0.0f);
    }
    __syncthreads();

    // ally outer products: 256 items = k(64) x f8(4), 8-wide
    {
        int k = t >> 2, f8 = (t & 3) * 8;
        float s[8] = {};
        #pragma unroll
        for (int n = 0; n < NA; n++) {
            float h = sm.b.ha[n][k];
            #pragma unroll
            for (int j = 0; j < 8; j++) s[j] += h * sm.b.fa[n][f8 + j];
        }
        emit8h(g_Ua, rb + k * AF + f8, s);
    }
    // enemy outer products: 448 items = k(64) x f4(7), 4-wide
    for (int it = t; it < 448; it += 256) {
        int k = it / 7, f4 = (it - k * 7) * 4;
        float s[4] = {};
        #pragma unroll
        for (int n = 0; n < NE; n++) {
            float h = sm.b.he[n][k];
            #pragma unroll
            for (int j = 0; j < 4; j++) s[j] += h * sm.b.fe[n][f4 + j];
        }
        emit4h(g_Ua, rb + OFF_ME + k * EF + f4, s);
    }
    if (t < 4) {
        int f8 = t * 8;
        float s[8] = {};
        #pragma unroll
        for (int n = 0; n < NA; n++)
            #pragma unroll
            for (int j = 0; j < 8; j++) s[j] += sm.b.fa[n][f8 + j];
        emit8h(g_Ua, rb + OFF_FA + f8, s);
    } else if (t >= 8 && t < 15) {
        int f4 = (t - 8) * 4;
        float s[4] = {};
        #pragma unroll
        for (int n = 0; n < NE; n++)
            #pragma unroll
            for (int j = 0; j < 4; j++) s[j] += sm.b.fe[n][f4 + j];
        emit4h(g_Ua, rb + OFF_FE + f4, s);
    } else if (t == 16) {
        float s[4] = {};
        emit4h(g_Ua, rb + KTOT, s);
    }
}

// ---------------------------------------------------------------------------
// Kernel 2: fp16 2-pass HMMA GEMM. BM=128, BN=64, BK=32, 2-stage cp.async,
// 256 threads / 8 warps, warp tile 32x32 (2mt x 4nt).
// Per kk: ldsm A, Bh, Bl; passes A*Bh then A*Bl (32 mma/stage, was 48).
// grid (8, 4, SPLIT=12) = 384 CTAs. Fused last-CTA split-K reduce.
// ---------------------------------------------------------------------------
#define ASTRIDE 40                       // fp16 elems per row (80 B)
#define ASZ1    (128 * ASTRIDE * 2)      // 10240 B per A stage
#define BSZ1    (64 * ASTRIDE * 2)       // 5120 B per B stage per array
#define OFF_A   0
#define OFF_BH  (2 * ASZ1)               // 20480
#define OFF_BL  (2 * ASZ1 + 2 * BSZ1)    // 30720
#define SMEM_DYN (2 * ASZ1 + 4 * BSZ1)   // 40960

__global__ void __launch_bounds__(256, 3) gemm_mma(float* __restrict__ out) {
    extern __shared__ char dsm[];
    __shared__ int s_old;
    const uint32_t sb = smem_u32(dsm);

    const int t    = threadIdx.x;
    const int lane = t & 31;
    const int wid  = t >> 5;
    const int wm   = (wid & 3) * 32;
    const int wn   = (wid >> 2) * 32;
    const int m0   = blockIdx.x * 128;
    const int n0   = blockIdx.y * 64;
    const int z    = blockIdx.z;
    const int s0   = (NST * z) / SPLIT;
    const int s1   = (NST * (z + 1)) / SPLIT;

    const int a_row = lane & 15;
    const int a_k8  = ((lane >> 4) & 1) * 8;
    const int b_row = (lane & 7) + ((lane >> 4) & 1) * 8;
    const int b_k8  = (lane & 8);

    float acc[2][4][4];
    #pragma unroll
    for (int i = 0; i < 2; i++)
        #pragma unroll
        for (int j = 0; j < 4; j++)
            #pragma unroll
            for (int q = 0; q < 4; q++) acc[i][j][q] = 0.0f;

    auto issue = [&](int s, int buf) {
        const int k0 = s * 32;
        #pragma unroll
        for (int q = 0; q < 2; q++) {
            int idx = t + q * 256;               // [0,512): A rows
            int m = idx >> 2, kc = idx & 3;
            uint32_t doff = (uint32_t)(m * ASTRIDE + kc * 8) * 2;
            cp16(sb + OFF_A + buf * ASZ1 + doff,
                 g_Ua + (size_t)(m0 + m) * KP + k0 + kc * 8);
        }
        {
            int n = t >> 2, kc = t & 3;
            uint32_t doff = (uint32_t)(n * ASTRIDE + kc * 8) * 2;
            const size_t goff = (size_t)(n0 + n) * KP + k0 + kc * 8;
            cp16(sb + OFF_BH + buf * BSZ1 + doff, g_Wt_h + goff);
            cp16(sb + OFF_BL + buf * BSZ1 + doff, g_Wt_l + goff);
        }
    };

    issue(s0, 0);
    CP_COMMIT();
    if (s0 + 1 < s1) issue(s0 + 1, 1);
    CP_COMMIT();

    int buf = 0;
    for (int s = s0; s < s1; s++) {
        CP_WAIT(1);            // stage s landed
        __syncthreads();

        const uint32_t baseA  = sb + OFF_A  + buf * ASZ1;
        const uint32_t baseBh = sb + OFF_BH + buf * BSZ1;
        const uint32_t baseBl = sb + OFF_BL + buf * BSZ1;

        #pragma unroll
        for (int kk = 0; kk < 2; kk++) {
            const int kcol = kk * 16;
            uint32_t A[2][4], Bh[4][2], Bl[4][2];
            #pragma unroll
            for (int p = 0; p < 2; p++) {
                uint32_t off = (uint32_t)((wn + p * 16 + b_row) * ASTRIDE + kcol + b_k8) * 2;
                ldsm4(Bh[2 * p][0], Bh[2 * p][1], Bh[2 * p + 1][0], Bh[2 * p + 1][1], baseBh + off);
                ldsm4(Bl[2 * p][0], Bl[2 * p][1], Bl[2 * p + 1][0], Bl[2 * p + 1][1], baseBl + off);
            }
            #pragma unroll
            for (int mt = 0; mt < 2; mt++) {
                uint32_t off = (uint32_t)((wm + mt * 16 + a_row) * ASTRIDE + kcol + a_k8) * 2;
                ldsm4(A[mt][0], A[mt][1], A[mt][2], A[mt][3], baseA + off);
            }
            // pass 1: A*Bh
            #pragma unroll
            for (int mt = 0; mt < 2; mt++)
                #pragma unroll
                for (int nt = 0; nt < 4; nt++)
                    mma_f16(acc[mt][nt], A[mt], Bh[nt]);
            // pass 2: A*Bl
            #pragma unroll
            for (int mt = 0; mt < 2; mt++)
                #pragma unroll
                for (int nt = 0; nt < 4; nt++)
                    mma_f16(acc[mt][nt], A[mt], Bl[nt]);
        }
        __syncthreads();       // compute(s) done: buf reusable

        if (s + 2 < s1) issue(s + 2, buf);
        CP_COMMIT();           // unconditional: uniform group counting
        buf ^= 1;
    }

    // write this CTA's split-K partial
    float* P = g_P + (size_t)z * (BATCH * OUTD);
    const int gr  = lane >> 2;
    const int tc2 = (lane & 3) * 2;
    #pragma unroll
    for (int mt = 0; mt < 2; mt++) {
        #pragma unroll
        for (int nt = 0; nt < 4; nt++) {
            int row = m0 + wm + mt * 16 + gr;
            int col = n0 + wn + nt * 8 + tc2;
            *(float2*)(P + (size_t)row * OUTD + col) =
                make_float2(acc[mt][nt][0], acc[mt][nt][1]);
            *(float2*)(P + (size_t)(row + 8) * OUTD + col) =
                make_float2(acc[mt][nt][2], acc[mt][nt][3]);
        }
    }

    // ---- fused split-K reduction: last CTA per (m,n) tile sums partials ----
    __threadfence();
    __syncthreads();
    const int tile = blockIdx.x * 4 + blockIdx.y;
    if (t == 0) s_old = atomicAdd(&g_cnt[tile], 1);
    __syncthreads();
    if (s_old == SPLIT - 1) {
        __threadfence();   // acquire: see peers' partials
        for (int i = t; i < 128 * 64 / 4; i += 256) {
            int r = i >> 4;
            int c = (i & 15) * 4;
            size_t off = (size_t)(m0 + r) * OUTD + n0 + c;
            float4 s = *(const float4*)(g_P + off);
            #pragma unroll
            for (int zz = 1; zz < SPLIT; zz++) {
                const float4 v = *(const float4*)(g_P + (size_t)zz * (BATCH * OUTD) + off);
                s.x += v.x; s.y += v.y; s.z += v.z; s.w += v.w;
            }
            *(float4*)(out + off) = s;
        }
        __syncthreads();
        if (t == 0) g_cnt[tile] = 0;   // reset for next graph replay
    }
}

// ---------------------------------------------------------------------------
// Inputs: 0 ally 1 enemy 2 wa1 3 ba1 4 wa2 5 ba2 6 we1 7 be1 8 we2 9 be2
// ---------------------------------------------------------------------------
extern "C" void kernel_launch(void* const* d_in, const int* in_sizes, int n_in,
                              void* d_out, int out_size) {
    const float* fa  = (const float*)d_in[0];
    const float* fe  = (const float*)d_in[1];
    const float* wa1 = (const float*)d_in[2];
    const float* ba1 = (const float*)d_in[3];
    const float* wa2 = (const float*)d_in[4];
    const float* ba2 = (const float*)d_in[5];
    const float* we1 = (const float*)d_in[6];
    const float* be1 = (const float*)d_in[7];
    const float* we2 = (const float*)d_in[8];
    const float* be2 = (const float*)d_in[9];
    float* out = (float*)d_out;

    cudaFuncSetAttribute(gemm_mma, cudaFuncAttributeMaxDynamicSharedMemorySize, SMEM_DYN);

    prep<<<BATCH + NPACK, 256>>>(fa, fe, wa1, ba1, wa2, ba2, we1, be1, we2, be2);
    gemm_mma<<<dim3(BATCH / 128, OUTD / 64, SPLIT), 256, SMEM_DYN>>>(out);
}

// round 14
// speedup vs baseline: 1.4384x; 1.1181x over previous
#include <cuda_runtime.h>
#include <cuda_fp16.h>
#include <stdint.h>

// Problem constants
#define BATCH 1024
#define NA    10
#define NE    11
#define AF    32
#define EF    28
#define HYP   64
#define OUTD  256

// Concatenated-K layout:
//   [0,2048) M_ally  [2048,2080) xsum_ally  [2080,3872) M_enemy
//   [3872,3900) xsum_enemy  [3900,3904) pad
#define KA      (HYP*AF)
#define OFF_FA  KA
#define OFF_ME  (KA+AF)
#define KE      (HYP*EF)
#define OFF_FE  (OFF_ME+KE)
#define KTOT    (OFF_FE+EF)
#define KP      3904
#define SPLIT   12
#define NST     (KP/32)        // 122 BK=32 stages
#define NPACK   ((KP/64)*4)    // 244 pack tiles

// fp16 operands (single precision level; combined rounding ~3e-4 rel err)
__device__ __align__(16) __half g_Ua[BATCH * KP];     // A [m][k]
__device__ __align__(16) __half g_Wt[OUTD * KP];      // B^T [n][k]
__device__ float g_P[SPLIT * BATCH * OUTD];           // split-K partials
__device__ int   g_cnt[32];                           // per-tile counters (zero-init)

// ---------------------------------------------------------------------------
// helpers
// ---------------------------------------------------------------------------
__device__ __forceinline__ uint32_t smem_u32(const void* p) {
    uint32_t a;
    asm("{ .reg .u64 t; cvta.to.shared.u64 t, %1; cvt.u32.u64 %0, t; }" : "=r"(a) : "l"(p));
    return a;
}
__device__ __forceinline__ void cp16(uint32_t dst, const void* src) {
    asm volatile("cp.async.cg.shared.global [%0], [%1], 16;" :: "r"(dst), "l"(src));
}
#define CP_COMMIT() asm volatile("cp.async.commit_group;" ::: "memory")
#define CP_WAIT(N)  asm volatile("cp.async.wait_group %0;" :: "n"(N) : "memory")

__device__ __forceinline__ void ldsm4(uint32_t& r0, uint32_t& r1, uint32_t& r2,
                                      uint32_t& r3, uint32_t addr) {
    asm volatile("ldmatrix.sync.aligned.m8n8.x4.shared.b16 {%0,%1,%2,%3}, [%4];"
                 : "=r"(r0), "=r"(r1), "=r"(r2), "=r"(r3) : "r"(addr));
}
__device__ __forceinline__ void mma_f16(float* c, const uint32_t* a, const uint32_t* b) {
    asm volatile(
        "mma.sync.aligned.m16n8k16.row.col.f32.f16.f16.f32 "
        "{%0,%1,%2,%3},{%4,%5,%6,%7},{%8,%9},{%0,%1,%2,%3};"
        : "+f"(c[0]), "+f"(c[1]), "+f"(c[2]), "+f"(c[3])
        : "r"(a[0]), "r"(a[1]), "r"(a[2]), "r"(a[3]), "r"(b[0]), "r"(b[1]));
}

// fp16 emitters
__device__ __forceinline__ void emit8h(__half* p, size_t idx, const float* v) {
    __align__(16) __half hv[8];
    #pragma unroll
    for (int j = 0; j < 8; j++) hv[j] = __float2half_rn(v[j]);
    *(uint4*)(p + idx) = *(const uint4*)hv;
}
__device__ __forceinline__ void emit4h(__half* p, size_t idx, const float* v) {
    __align__(8) __half hv[4];
    #pragma unroll
    for (int j = 0; j < 4; j++) hv[j] = __float2half_rn(v[j]);
    *(uint2*)(p + idx) = *(const uint2*)hv;
}

// ---------------------------------------------------------------------------
// Kernel 1 "prep": blocks [0,BATCH) build U; [BATCH,BATCH+NPACK) pack Wt.
// ---------------------------------------------------------------------------
struct PrepSmem {
    union {
        float pack_s[64][65];
        struct {
            float wa1[AF * HYP];
            float we1[EF * HYP];
            float fa[NA][AF];
            float fe[NE][EF];
            float ha[NA][HYP];
            float he[NE][HYP];
        } b;
    };
};

__global__ __launch_bounds__(256) void prep(
    const float* __restrict__ fa, const float* __restrict__ fe,
    const float* __restrict__ wa1, const float* __restrict__ ba1,
    const float* __restrict__ wa2, const float* __restrict__ ba2,
    const float* __restrict__ we1, const float* __restrict__ be1,
    const float* __restrict__ we2, const float* __restrict__ be2) {

    __shared__ PrepSmem sm;
    const int t = threadIdx.x;

    if (blockIdx.x >= BATCH) {
        // ---- pack: transpose + convert combined weight into Wt[n][k] ----
        const int pb = blockIdx.x - BATCH;
        const int k0 = (pb >> 2) * 64;
        const int n0 = (pb & 3) * 64;

        for (int i = t; i < 64 * 64; i += 256) {
            int kl = i >> 6, nl = i & 63;
            int r = k0 + kl, n = n0 + nl;
            float v;
            if (r < KA)            v = wa2[(size_t)r * OUTD + n];
            else if (r < OFF_ME)   v = ba2[(size_t)(r - KA) * OUTD + n];
            else if (r < OFF_FE)   v = we2[(size_t)(r - OFF_ME) * OUTD + n];
            else if (r < KTOT)     v = be2[(size_t)(r - OFF_FE) * OUTD + n];
            else                   v = 0.0f;
            sm.pack_s[kl][nl] = v;
        }
        __syncthreads();
        for (int i = t; i < 512; i += 256) {
            int nl = i >> 3, kl8 = (i & 7) * 8;
            float v[8];
            #pragma unroll
            for (int j = 0; j < 8; j++) v[j] = sm.pack_s[kl8 + j][nl];
            emit8h(g_Wt, (size_t)(n0 + nl) * KP + k0 + kl8, v);
        }
        return;
    }

    // ---- build U for batch element b ----
    const int b = blockIdx.x;
    const size_t rb = (size_t)b * KP;

    for (int i = t; i < AF * HYP; i += 256) sm.b.wa1[i] = wa1[i];
    for (int i = t; i < EF * HYP; i += 256) sm.b.we1[i] = we1[i];
    for (int i = t; i < NA * AF; i += 256) sm.b.fa[i / AF][i % AF] = fa[b * NA * AF + i];
    for (int i = t; i < NE * EF; i += 256) sm.b.fe[i / EF][i % EF] = fe[b * NE * EF + i];
    __syncthreads();

    for (int i = t; i < NA * HYP; i += 256) {
        int n = i / HYP, k = i % HYP;
        float s = ba1[k];
        #pragma unroll
        for (int f = 0; f < AF; f++) s += sm.b.fa[n][f] * sm.b.wa1[f * HYP + k];
        sm.b.ha[n][k] = fmaxf(s, 0.0f);
    }
    for (int i = t; i < NE * HYP; i += 256) {
        int n = i / HYP, k = i % HYP;
        float s = be1[k];
        #pragma unroll
        for (int f = 0; f < EF; f++) s += sm.b.fe[n][f] * sm.b.we1[f * HYP + k];
        sm.b.he[n][k] = fmaxf(s, 0.0f);
    }
    __syncthreads();

    // ally outer products: 256 items = k(64) x f8(4), 8-wide
    {
        int k = t >> 2, f8 = (t & 3) * 8;
        float s[8] = {};
        #pragma unroll
        for (int n = 0; n < NA; n++) {
            float h = sm.b.ha[n][k];
            #pragma unroll
            for (int j = 0; j < 8; j++) s[j] += h * sm.b.fa[n][f8 + j];
        }
        emit8h(g_Ua, rb + k * AF + f8, s);
    }
    // enemy outer products: 448 items = k(64) x f4(7), 4-wide
    for (int it = t; it < 448; it += 256) {
        int k = it / 7, f4 = (it - k * 7) * 4;
        float s[4] = {};
        #pragma unroll
        for (int n = 0; n < NE; n++) {
            float h = sm.b.he[n][k];
            #pragma unroll
            for (int j = 0; j < 4; j++) s[j] += h * sm.b.fe[n][f4 + j];
        }
        emit4h(g_Ua, rb + OFF_ME + k * EF + f4, s);
    }
    if (t < 4) {
        int f8 = t * 8;
        float s[8] = {};
        #pragma unroll
        for (int n = 0; n < NA; n++)
            #pragma unroll
            for (int j = 0; j < 8; j++) s[j] += sm.b.fa[n][f8 + j];
        emit8h(g_Ua, rb + OFF_FA + f8, s);
    } else if (t >= 8 && t < 15) {
        int f4 = (t - 8) * 4;
        float s[4] = {};
        #pragma unroll
        for (int n = 0; n < NE; n++)
            #pragma unroll
            for (int j = 0; j < 4; j++) s[j] += sm.b.fe[n][f4 + j];
        emit4h(g_Ua, rb + OFF_FE + f4, s);
    } else if (t == 16) {
        float s[4] = {};
        emit4h(g_Ua, rb + KTOT, s);
    }
}

// ---------------------------------------------------------------------------
// Kernel 2: single-pass fp16 HMMA GEMM. BM=128, BN=64, BK=32, 2-stage
// cp.async, 256 threads / 8 warps, warp tile 32x32 (2mt x 4nt).
// Per kk: 2 A-ldsm + 2 B-ldsm + 8 mma. grid (8, 4, SPLIT=12) = 384 CTAs.
// Fused last-CTA split-K reduce.
// ---------------------------------------------------------------------------
#define ASTRIDE 40                       // fp16 elems per row (80 B)
#define ASZ1    (128 * ASTRIDE * 2)      // 10240 B per A stage
#define BSZ1    (64 * ASTRIDE * 2)       // 5120 B per B stage
#define OFF_A   0
#define OFF_B   (2 * ASZ1)               // 20480
#define SMEM_DYN (2 * ASZ1 + 2 * BSZ1)   // 30720

__global__ void __launch_bounds__(256, 3) gemm_mma(float* __restrict__ out) {
    extern __shared__ char dsm[];
    __shared__ int s_old;
    const uint32_t sb = smem_u32(dsm);

    const int t    = threadIdx.x;
    const int lane = t & 31;
    const int wid  = t >> 5;
    const int wm   = (wid & 3) * 32;
    const int wn   = (wid >> 2) * 32;
    const int m0   = blockIdx.x * 128;
    const int n0   = blockIdx.y * 64;
    const int z    = blockIdx.z;
    const int s0   = (NST * z) / SPLIT;
    const int s1   = (NST * (z + 1)) / SPLIT;

    const int a_row = lane & 15;
    const int a_k8  = ((lane >> 4) & 1) * 8;
    const int b_row = (lane & 7) + ((lane >> 4) & 1) * 8;
    const int b_k8  = (lane & 8);

    float acc[2][4][4];
    #pragma unroll
    for (int i = 0; i < 2; i++)
        #pragma unroll
        for (int j = 0; j < 4; j++)
            #pragma unroll
            for (int q = 0; q < 4; q++) acc[i][j][q] = 0.0f;

    auto issue = [&](int s, int buf) {
        const int k0 = s * 32;
        #pragma unroll
        for (int q = 0; q < 2; q++) {
            int idx = t + q * 256;               // [0,512): A rows
            int m = idx >> 2, kc = idx & 3;
            uint32_t doff = (uint32_t)(m * ASTRIDE + kc * 8) * 2;
            cp16(sb + OFF_A + buf * ASZ1 + doff,
                 g_Ua + (size_t)(m0 + m) * KP + k0 + kc * 8);
        }
        {
            int n = t >> 2, kc = t & 3;
            uint32_t doff = (uint32_t)(n * ASTRIDE + kc * 8) * 2;
            cp16(sb + OFF_B + buf * BSZ1 + doff,
                 g_Wt + (size_t)(n0 + n) * KP + k0 + kc * 8);
        }
    };

    issue(s0, 0);
    CP_COMMIT();
    if (s0 + 1 < s1) issue(s0 + 1, 1);
    CP_COMMIT();

    int buf = 0;
    for (int s = s0; s < s1; s++) {
        CP_WAIT(1);            // stage s landed
        __syncthreads();

        const uint32_t baseA = sb + OFF_A + buf * ASZ1;
        const uint32_t baseB = sb + OFF_B + buf * BSZ1;

        #pragma unroll
        for (int kk = 0; kk < 2; kk++) {
            const int kcol = kk * 16;
            uint32_t A[2][4], B[4][2];
            #pragma unroll
            for (int p = 0; p < 2; p++) {
                uint32_t off = (uint32_t)((wn + p * 16 + b_row) * ASTRIDE + kcol + b_k8) * 2;
                ldsm4(B[2 * p][0], B[2 * p][1], B[2 * p + 1][0], B[2 * p + 1][1], baseB + off);
            }
            #pragma unroll
            for (int mt = 0; mt < 2; mt++) {
                uint32_t off = (uint32_t)((wm + mt * 16 + a_row) * ASTRIDE + kcol + a_k8) * 2;
                ldsm4(A[mt][0], A[mt][1], A[mt][2], A[mt][3], baseA + off);
            }
            #pragma unroll
            for (int mt = 0; mt < 2; mt++)
                #pragma unroll
                for (int nt = 0; nt < 4; nt++)
                    mma_f16(acc[mt][nt], A[mt], B[nt]);
        }
        __syncthreads();       // compute(s) done: buf reusable

        if (s + 2 < s1) issue(s + 2, buf);
        CP_COMMIT();           // unconditional: uniform group counting
        buf ^= 1;
    }

    // write this CTA's split-K partial
    float* P = g_P + (size_t)z * (BATCH * OUTD);
    const int gr  = lane >> 2;
    const int tc2 = (lane & 3) * 2;
    #pragma unroll
    for (int mt = 0; mt < 2; mt++) {
        #pragma unroll
        for (int nt = 0; nt < 4; nt++) {
            int row = m0 + wm + mt * 16 + gr;
            int col = n0 + wn + nt * 8 + tc2;
            *(float2*)(P + (size_t)row * OUTD + col) =
                make_float2(acc[mt][nt][0], acc[mt][nt][1]);
            *(float2*)(P + (size_t)(row + 8) * OUTD + col) =
                make_float2(acc[mt][nt][2], acc[mt][nt][3]);
        }
    }

    // ---- fused split-K reduction: last CTA per (m,n) tile sums partials ----
    __threadfence();
    __syncthreads();
    const int tile = blockIdx.x * 4 + blockIdx.y;
    if (t == 0) s_old = atomicAdd(&g_cnt[tile], 1);
    __syncthreads();
    if (s_old == SPLIT - 1) {
        __threadfence();   // acquire: see peers' partials
        for (int i = t; i < 128 * 64 / 4; i += 256) {
            int r = i >> 4;
            int c = (i & 15) * 4;
            size_t off = (size_t)(m0 + r) * OUTD + n0 + c;
            float4 s = *(const float4*)(g_P + off);
            #pragma unroll
            for (int zz = 1; zz < SPLIT; zz++) {
                const float4 v = *(const float4*)(g_P + (size_t)zz * (BATCH * OUTD) + off);
                s.x += v.x; s.y += v.y; s.z += v.z; s.w += v.w;
            }
            *(float4*)(out + off) = s;
        }
        __syncthreads();
        if (t == 0) g_cnt[tile] = 0;   // reset for next graph replay
    }
}

// ---------------------------------------------------------------------------
// Inputs: 0 ally 1 enemy 2 wa1 3 ba1 4 wa2 5 ba2 6 we1 7 be1 8 we2 9 be2
// ---------------------------------------------------------------------------
extern "C" void kernel_launch(void* const* d_in, const int* in_sizes, int n_in,
                              void* d_out, int out_size) {
    const float* fa  = (const float*)d_in[0];
    const float* fe  = (const float*)d_in[1];
    const float* wa1 = (const float*)d_in[2];
    const float* ba1 = (const float*)d_in[3];
    const float* wa2 = (const float*)d_in[4];
    const float* ba2 = (const float*)d_in[5];
    const float* we1 = (const float*)d_in[6];
    const float* be1 = (const float*)d_in[7];
    const float* we2 = (const float*)d_in[8];
    const float* be2 = (const float*)d_in[9];
    float* out = (float*)d_out;

    cudaFuncSetAttribute(gemm_mma, cudaFuncAttributeMaxDynamicSharedMemorySize, SMEM_DYN);

    prep<<<BATCH + NPACK, 256>>>(fa, fe, wa1, ba1, wa2, ba2, we1, be1, we2, be2);
    gemm_mma<<<dim3(BATCH / 128, OUTD / 64, SPLIT), 256, SMEM_DYN>>>(out);
}

// round 15
// speedup vs baseline: 1.5118x; 1.0510x over previous
#include <cuda_runtime.h>
#include <cuda_fp16.h>
#include <stdint.h>

// Problem constants
#define BATCH 1024
#define NA    10
#define NE    11
#define AF    32
#define EF    28
#define HYP   64
#define OUTD  256

// Concatenated-K layout:
//   [0,2048) M_ally  [2048,2080) xsum_ally  [2080,3872) M_enemy
//   [3872,3900) xsum_enemy  [3900,3904) pad
#define KA      (HYP*AF)
#define OFF_FA  KA
#define OFF_ME  (KA+AF)
#define KE      (HYP*EF)
#define OFF_FE  (OFF_ME+KE)
#define KTOT    (OFF_FE+EF)
#define KP      3904
#define SPLIT   12
#define BK      64
#define NST     (KP/BK)        // 61 stages
#define NPACK   ((KP/64)*4)    // 244 pack tiles

// fp16 operands (combined rounding ~3e-4 rel err, validated R13)
__device__ __align__(16) __half g_Ua[BATCH * KP];     // A [m][k]
__device__ __align__(16) __half g_Wt[OUTD * KP];      // B^T [n][k]
__device__ float g_P[SPLIT * BATCH * OUTD];           // split-K partials
__device__ int   g_cnt[32];                           // per-tile counters (zero-init)

// ---------------------------------------------------------------------------
// helpers
// ---------------------------------------------------------------------------
__device__ __forceinline__ uint32_t smem_u32(const void* p) {
    uint32_t a;
    asm("{ .reg .u64 t; cvta.to.shared.u64 t, %1; cvt.u32.u64 %0, t; }" : "=r"(a) : "l"(p));
    return a;
}
__device__ __forceinline__ void cp16(uint32_t dst, const void* src) {
    asm volatile("cp.async.cg.shared.global [%0], [%1], 16;" :: "r"(dst), "l"(src));
}
#define CP_COMMIT() asm volatile("cp.async.commit_group;" ::: "memory")
#define CP_WAIT(N)  asm volatile("cp.async.wait_group %0;" :: "n"(N) : "memory")

__device__ __forceinline__ void ldsm4(uint32_t& r0, uint32_t& r1, uint32_t& r2,
                                      uint32_t& r3, uint32_t addr) {
    asm volatile("ldmatrix.sync.aligned.m8n8.x4.shared.b16 {%0,%1,%2,%3}, [%4];"
                 : "=r"(r0), "=r"(r1), "=r"(r2), "=r"(r3) : "r"(addr));
}
__device__ __forceinline__ void mma_f16(float* c, const uint32_t* a, const uint32_t* b) {
    asm volatile(
        "mma.sync.aligned.m16n8k16.row.col.f32.f16.f16.f32 "
        "{%0,%1,%2,%3},{%4,%5,%6,%7},{%8,%9},{%0,%1,%2,%3};"
        : "+f"(c[0]), "+f"(c[1]), "+f"(c[2]), "+f"(c[3])
        : "r"(a[0]), "r"(a[1]), "r"(a[2]), "r"(a[3]), "r"(b[0]), "r"(b[1]));
}

// fp16 emitters
__device__ __forceinline__ void emit8h(__half* p, size_t idx, const float* v) {
    __align__(16) __half hv[8];
    #pragma unroll
    for (int j = 0; j < 8; j++) hv[j] = __float2half_rn(v[j]);
    *(uint4*)(p + idx) = *(const uint4*)hv;
}
__device__ __forceinline__ void emit4h(__half* p, size_t idx, const float* v) {
    __align__(8) __half hv[4];
    #pragma unroll
    for (int j = 0; j < 4; j++) hv[j] = __float2half_rn(v[j]);
    *(uint2*)(p + idx) = *(const uint2*)hv;
}

// ---------------------------------------------------------------------------
// Kernel 1 "prep": blocks [0,BATCH) build U; [BATCH,BATCH+NPACK) pack Wt.
// Weight matrices staged TRANSPOSED ([k][f], 36-float padded rows) so the
// hidden-layer inner products read both operands via LDS.128.
// ---------------------------------------------------------------------------
#define WSTR 36   // padded row stride (floats): 144 B, 16B-aligned, 4-way STS only

struct PrepSmem {
    union {
        float pack_s[64][65];
        struct {
            float wa1t[HYP * WSTR];   // [k][f] f<32
            float we1t[HYP * WSTR];   // [k][f] f<28
            float fa[NA][AF];
            float fe[NE][EF];
            float ha[NA][HYP];
            float he[NE][HYP];
        } b;
    };
};

__global__ __launch_bounds__(256) void prep(
    const float* __restrict__ fa, const float* __restrict__ fe,
    const float* __restrict__ wa1, const float* __restrict__ ba1,
    const float* __restrict__ wa2, const float* __restrict__ ba2,
    const float* __restrict__ we1, const float* __restrict__ be1,
    const float* __restrict__ we2, const float* __restrict__ be2) {

    __shared__ PrepSmem sm;
    const int t = threadIdx.x;

    if (blockIdx.x >= BATCH) {
        // ---- pack: transpose + convert combined weight into Wt[n][k] ----
        const int pb = blockIdx.x - BATCH;
        const int k0 = (pb >> 2) * 64;
        const int n0 = (pb & 3) * 64;

        for (int i = t; i < 64 * 64; i += 256) {
            int kl = i >> 6, nl = i & 63;
            int r = k0 + kl, n = n0 + nl;
            float v;
            if (r < KA)            v = wa2[(size_t)r * OUTD + n];
            else if (r < OFF_ME)   v = ba2[(size_t)(r - KA) * OUTD + n];
            else if (r < OFF_FE)   v = we2[(size_t)(r - OFF_ME) * OUTD + n];
            else if (r < KTOT)     v = be2[(size_t)(r - OFF_FE) * OUTD + n];
            else                   v = 0.0f;
            sm.pack_s[kl][nl] = v;
        }
        __syncthreads();
        for (int i = t; i < 512; i += 256) {
            int nl = i >> 3, kl8 = (i & 7) * 8;
            float v[8];
            #pragma unroll
            for (int j = 0; j < 8; j++) v[j] = sm.pack_s[kl8 + j][nl];
            emit8h(g_Wt, (size_t)(n0 + nl) * KP + k0 + kl8, v);
        }
        return;
    }

    // ---- build U for batch element b ----
    const int b = blockIdx.x;
    const size_t rb = (size_t)b * KP;

    // stage weights transposed: wa1 is [f][k] row-major -> wa1t[k][f]
    for (int i = t; i < AF * HYP; i += 256) {
        int f = i >> 6, k = i & 63;
        sm.b.wa1t[k * WSTR + f] = wa1[i];
    }
    for (int i = t; i < EF * HYP; i += 256) {
        int f = i >> 6, k = i & 63;
        sm.b.we1t[k * WSTR + f] = we1[i];
    }
    for (int i = t; i < NA * AF; i += 256) sm.b.fa[i / AF][i % AF] = fa[b * NA * AF + i];
    for (int i = t; i < NE * EF; i += 256) sm.b.fe[i / EF][i % EF] = fe[b * NE * EF + i];
    __syncthreads();

    // hidden layers — both operand rows contiguous, vectorized
    for (int i = t; i < NA * HYP; i += 256) {
        int n = i / HYP, k = i % HYP;
        const float4* wr = (const float4*)&sm.b.wa1t[k * WSTR];
        const float4* xr = (const float4*)&sm.b.fa[n][0];
        float s = ba1[k];
        #pragma unroll
        for (int q = 0; q < 8; q++) {
            float4 w = wr[q], x = xr[q];
            s += x.x * w.x + x.y * w.y + x.z * w.z + x.w * w.w;
        }
        sm.b.ha[n][k] = fmaxf(s, 0.0f);
    }
    for (int i = t; i < NE * HYP; i += 256) {
        int n = i / HYP, k = i % HYP;
        const float4* wr = (const float4*)&sm.b.we1t[k * WSTR];
        const float4* xr = (const float4*)&sm.b.fe[n][0];
        float s = be1[k];
        #pragma unroll
        for (int q = 0; q < 7; q++) {
            float4 w = wr[q], x = xr[q];
            s += x.x * w.x + x.y * w.y + x.z * w.z + x.w * w.w;
        }
        sm.b.he[n][k] = fmaxf(s, 0.0f);
    }
    __syncthreads();

    // ally outer products: 256 items = k(64) x f8(4), 8-wide
    {
        int k = t >> 2, f8 = (t & 3) * 8;
        float s[8] = {};
        #pragma unroll
        for (int n = 0; n < NA; n++) {
            float h = sm.b.ha[n][k];
            #pragma unroll
            for (int j = 0; j < 8; j++) s[j] += h * sm.b.fa[n][f8 + j];
        }
        emit8h(g_Ua, rb + k * AF + f8, s);
    }
    // enemy outer products: 448 items = k(64) x f4(7), 4-wide
    for (int it = t; it < 448; it += 256) {
        int k = it / 7, f4 = (it - k * 7) * 4;
        float s[4] = {};
        #pragma unroll
        for (int n = 0; n < NE; n++) {
            float h = sm.b.he[n][k];
            #pragma unroll
            for (int j = 0; j < 4; j++) s[j] += h * sm.b.fe[n][f4 + j];
        }
        emit4h(g_Ua, rb + OFF_ME + k * EF + f4, s);
    }
    if (t < 4) {
        int f8 = t * 8;
        float s[8] = {};
        #pragma unroll
        for (int n = 0; n < NA; n++)
            #pragma unroll
            for (int j = 0; j < 8; j++) s[j] += sm.b.fa[n][f8 + j];
        emit8h(g_Ua, rb + OFF_FA + f8, s);
    } else if (t >= 8 && t < 15) {
        int f4 = (t - 8) * 4;
        float s[4] = {};
        #pragma unroll
        for (int n = 0; n < NE; n++)
            #pragma unroll
            for (int j = 0; j < 4; j++) s[j] += sm.b.fe[n][f4 + j];
        emit4h(g_Ua, rb + OFF_FE + f4, s);
    } else if (t == 16) {
        float s[4] = {};
        emit4h(g_Ua, rb + KTOT, s);
    }
}

// ---------------------------------------------------------------------------
// Kernel 2: single-pass fp16 HMMA GEMM. BM=128, BN=64, BK=64, 2-stage
// cp.async, 256 threads / 8 warps, warp tile 32x32 (2mt x 4nt).
// 61 stages total, ~5 per split-K slab. grid (8, 4, SPLIT=12) = 384 CTAs.
// Fused last-CTA split-K reduce.
// ---------------------------------------------------------------------------
#define ASTRIDE 72                       // fp16 elems per row (144 B, ldsm-clean)
#define ASZ1    (128 * ASTRIDE * 2)      // 18432 B per A stage
#define BSZ1    (64 * ASTRIDE * 2)       // 9216 B per B stage
#define OFF_A   0
#define OFF_B   (2 * ASZ1)               // 36864
#define SMEM_DYN (2 * ASZ1 + 2 * BSZ1)   // 55296

__global__ void __launch_bounds__(256, 3) gemm_mma(float* __restrict__ out) {
    extern __shared__ char dsm[];
    __shared__ int s_old;
    const uint32_t sb = smem_u32(dsm);

    const int t    = threadIdx.x;
    const int lane = t & 31;
    const int wid  = t >> 5;
    const int wm   = (wid & 3) * 32;
    const int wn   = (wid >> 2) * 32;
    const int m0   = blockIdx.x * 128;
    const int n0   = blockIdx.y * 64;
    const int z    = blockIdx.z;
    const int s0   = (NST * z) / SPLIT;
    const int s1   = (NST * (z + 1)) / SPLIT;

    const int a_row = lane & 15;
    const int a_k8  = ((lane >> 4) & 1) * 8;
    const int b_row = (lane & 7) + ((lane >> 4) & 1) * 8;
    const int b_k8  = (lane & 8);

    float acc[2][4][4];
    #pragma unroll
    for (int i = 0; i < 2; i++)
        #pragma unroll
        for (int j = 0; j < 4; j++)
            #pragma unroll
            for (int q = 0; q < 4; q++) acc[i][j][q] = 0.0f;

    auto issue = [&](int s, int buf) {
        const int k0 = s * BK;
        #pragma unroll
        for (int q = 0; q < 4; q++) {
            int idx = t + q * 256;               // [0,1024): A 128 rows x 8 chunks
            int m = idx >> 3, kc = idx & 7;
            uint32_t doff = (uint32_t)(m * ASTRIDE + kc * 8) * 2;
            cp16(sb + OFF_A + buf * ASZ1 + doff,
                 g_Ua + (size_t)(m0 + m) * KP + k0 + kc * 8);
        }
        #pragma unroll
        for (int q = 0; q < 2; q++) {
            int idx = t + q * 256;               // [0,512): B 64 rows x 8 chunks
            int n = idx >> 3, kc = idx & 7;
            uint32_t doff = (uint32_t)(n * ASTRIDE + kc * 8) * 2;
            cp16(sb + OFF_B + buf * BSZ1 + doff,
                 g_Wt + (size_t)(n0 + n) * KP + k0 + kc * 8);
        }
    };

    issue(s0, 0);
    CP_COMMIT();
    if (s0 + 1 < s1) issue(s0 + 1, 1);
    CP_COMMIT();

    int buf = 0;
    for (int s = s0; s < s1; s++) {
        CP_WAIT(1);            // stage s landed
        __syncthreads();

        const uint32_t baseA = sb + OFF_A + buf * ASZ1;
        const uint32_t baseB = sb + OFF_B + buf * BSZ1;

        #pragma unroll
        for (int kk = 0; kk < 4; kk++) {
            const int kcol = kk * 16;
            uint32_t A[2][4], B[4][2];
            #pragma unroll
            for (int p = 0; p < 2; p++) {
                uint32_t off = (uint32_t)((wn + p * 16 + b_row) * ASTRIDE + kcol + b_k8) * 2;
                ldsm4(B[2 * p][0], B[2 * p][1], B[2 * p + 1][0], B[2 * p + 1][1], baseB + off);
            }
            #pragma unroll
            for (int mt = 0; mt < 2; mt++) {
                uint32_t off = (uint32_t)((wm + mt * 16 + a_row) * ASTRIDE + kcol + a_k8) * 2;
                ldsm4(A[mt][0], A[mt][1], A[mt][2], A[mt][3], baseA + off);
            }
            #pragma unroll
            for (int mt = 0; mt < 2; mt++)
                #pragma unroll
                for (int nt = 0; nt < 4; nt++)
                    mma_f16(acc[mt][nt], A[mt], B[nt]);
        }
        __syncthreads();       // compute(s) done: buf reusable

        if (s + 2 < s1) issue(s + 2, buf);
        CP_COMMIT();           // unconditional: uniform group counting
        buf ^= 1;
    }

    // write this CTA's split-K partial
    float* P = g_P + (size_t)z * (BATCH * OUTD);
    const int gr  = lane >> 2;
    const int tc2 = (lane & 3) * 2;
    #pragma unroll
    for (int mt = 0; mt < 2; mt++) {
        #pragma unroll
        for (int nt = 0; nt < 4; nt++) {
            int row = m0 + wm + mt * 16 + gr;
            int col = n0 + wn + nt * 8 + tc2;
            *(float2*)(P + (size_t)row * OUTD + col) =
                make_float2(acc[mt][nt][0], acc[mt][nt][1]);
            *(float2*)(P + (size_t)(row + 8) * OUTD + col) =
                make_float2(acc[mt][nt][2], acc[mt][nt][3]);
        }
    }

    // ---- fused split-K reduction: last CTA per (m,n) tile sums partials ----
    __threadfence();
    __syncthreads();
    const int tile = blockIdx.x * 4 + blockIdx.y;
    if (t == 0) s_old = atomicAdd(&g_cnt[tile], 1);
    __syncthreads();
    if (s_old == SPLIT - 1) {
        __threadfence();   // acquire: see peers' partials
        for (int i = t; i < 128 * 64 / 4; i += 256) {
            int r = i >> 4;
            int c = (i & 15) * 4;
            size_t off = (size_t)(m0 + r) * OUTD + n0 + c;
            float4 s = *(const float4*)(g_P + off);
            #pragma unroll
            for (int zz = 1; zz < SPLIT; zz++) {
                const float4 v = *(const float4*)(g_P + (size_t)zz * (BATCH * OUTD) + off);
                s.x += v.x; s.y += v.y; s.z += v.z; s.w += v.w;
            }
            *(float4*)(out + off) = s;
        }
        __syncthreads();
        if (t == 0) g_cnt[tile] = 0;   // reset for next graph replay
    }
}

// ---------------------------------------------------------------------------
// Inputs: 0 ally 1 enemy 2 wa1 3 ba1 4 wa2 5 ba2 6 we1 7 be1 8 we2 9 be2
// ---------------------------------------------------------------------------
extern "C" void kernel_launch(void* const* d_in, const int* in_sizes, int n_in,
                              void* d_out, int out_size) {
    const float* fa  = (const float*)d_in[0];
    const float* fe  = (const float*)d_in[1];
    const float* wa1 = (const float*)d_in[2];
    const float* ba1 = (const float*)d_in[3];
    const float* wa2 = (const float*)d_in[4];
    const float* ba2 = (const float*)d_in[5];
    const float* we1 = (const float*)d_in[6];
    const float* be1 = (const float*)d_in[7];
    const float* we2 = (const float*)d_in[8];
    const float* be2 = (const float*)d_in[9];
    float* out = (float*)d_out;

    cudaFuncSetAttribute(gemm_mma, cudaFuncAttributeMaxDynamicSharedMemorySize, SMEM_DYN);

    prep<<<BATCH + NPACK, 256>>>(fa, fe, wa1, ba1, wa2, ba2, we1, be1, we2, be2);
    gemm_mma<<<dim3(BATCH / 128, OUTD / 64, SPLIT), 256, SMEM_DYN>>>(out);
}